// round 13
// baseline (speedup 1.0000x reference)
#include <cuda_runtime.h>
#include <cuda_bf16.h>
#include <cstdint>
#include <math.h>

#define TT  2048
#define BB  2
#define NHH 8

#define OFF_INW   0
#define OFF_OUTW  786432
#define OFF_POSW  1048576
#define OFF_INB   1310720
#define OFF_OUTB  1312256
#define OFF_POSB  1312768
#define OFF_RWB   1313280
#define OFF_RRB   1313792
#define N_W       1314304

typedef unsigned long long u64;
typedef unsigned int u32;

__device__ __forceinline__ u32 s2u(const void* p) {
    u32 a;
    asm("{.reg .u64 t; cvta.to.shared.u64 t, %1; cvt.u32.u64 %0, t;}" : "=r"(a) : "l"(p));
    return a;
}
__device__ __forceinline__ void ldm4(u32* r, u32 addr) {
    asm volatile("ldmatrix.sync.aligned.m8n8.x4.shared.b16 {%0,%1,%2,%3}, [%4];"
        : "=r"(r[0]), "=r"(r[1]), "=r"(r[2]), "=r"(r[3]) : "r"(addr));
}
__device__ __forceinline__ void ldm4t(u32* r, u32 addr) {
    asm volatile("ldmatrix.sync.aligned.m8n8.x4.trans.shared.b16 {%0,%1,%2,%3}, [%4];"
        : "=r"(r[0]), "=r"(r[1]), "=r"(r[2]), "=r"(r[3]) : "r"(addr));
}
__device__ __forceinline__ void mma_bf16(float* c, const u32* a, u32 b0, u32 b1) {
    asm volatile("mma.sync.aligned.m16n8k16.row.col.f32.bf16.bf16.f32 "
        "{%0,%1,%2,%3}, {%4,%5,%6,%7}, {%8,%9}, {%0,%1,%2,%3};"
        : "+f"(c[0]), "+f"(c[1]), "+f"(c[2]), "+f"(c[3])
        : "r"(a[0]), "r"(a[1]), "r"(a[2]), "r"(a[3]), "r"(b0), "r"(b1));
}
__device__ __forceinline__ u32 swz(u32 b) { return b ^ ((b >> 3) & 0x70); }

__device__ __forceinline__ u64 pk2(float lo, float hi) {
    u64 r; asm("mov.b64 %0, {%1, %2};" : "=l"(r) : "f"(lo), "f"(hi)); return r;
}
__device__ __forceinline__ u64 splat2(float x) {
    u64 r; asm("mov.b64 %0, {%1, %1};" : "=l"(r) : "f"(x)); return r;
}
__device__ __forceinline__ u64 ffma2(u64 a, u64 b, u64 c) {
    u64 d; asm("fma.rn.f32x2 %0, %1, %2, %3;" : "=l"(d) : "l"(a), "l"(b), "l"(c));
    return d;
}
__device__ __forceinline__ void upk2u(u64 v, u32& lo, u32& hi) {
    asm("mov.b64 {%0, %1}, %2;" : "=r"(lo), "=r"(hi) : "l"(v));
}

// packed exp(y0), exp(y1) for y in [-87, 0]: y pre-shifted by -mnew (exact sub).
// magic-constant n/f split; deg-5 2^f poly; exponent splice.
__device__ __forceinline__ void exp2pair(float y0, float y1, float& e0, float& e1) {
    const u64 L2E2 = splat2(1.44269504088896f);
    const u64 MAGIC = splat2(12582912.0f);
    u64 y2 = pk2(y0, y1);
    u64 t2 = ffma2(y2, L2E2, MAGIC);
    u64 s2 = ffma2(t2, splat2(-1.f), MAGIC);   // MAGIC - t (exact)
    u64 f2 = ffma2(y2, L2E2, s2);              // f = y*log2e - n
    u64 p2 = ffma2(f2, splat2(1.3333558e-3f), splat2(9.6181291e-3f));
    p2 = ffma2(f2, p2, splat2(5.5504109e-2f));
    p2 = ffma2(f2, p2, splat2(2.4022651e-1f));
    p2 = ffma2(f2, p2, splat2(6.9314718e-1f));
    p2 = ffma2(f2, p2, splat2(1.0f));
    u32 tl, th, pl, ph;
    upk2u(t2, tl, th);
    upk2u(p2, pl, ph);
    e0 = __uint_as_float(pl + (tl << 23));
    e1 = __uint_as_float(ph + (th << 23));
}

__device__ __forceinline__ void hl2(float x, float y, u32& h, u32& l) {
    __nv_bfloat16 hx = __float2bfloat16(x), hy = __float2bfloat16(y);
    __nv_bfloat16 lx = __float2bfloat16(x - __bfloat162float(hx));
    __nv_bfloat16 ly = __float2bfloat16(y - __bfloat162float(hy));
    __nv_bfloat162 hh = __halves2bfloat162(hx, hy), ll = __halves2bfloat162(lx, ly);
    h = *(u32*)&hh; l = *(u32*)&ll;
}
__device__ __forceinline__ void cvt8(float4 a, float4 b2, uint4& h, uint4& l) {
    hl2(a.x, a.y, h.x, l.x); hl2(a.z, a.w, h.y, l.y);
    hl2(b2.x, b2.y, h.z, l.z); hl2(b2.z, b2.w, h.w, l.w);
}

__device__ float g_w[N_W];
__device__ float g_qkv[(size_t)TT * BB * 3 * 512];
__device__ float g_r[(size_t)TT * 512];
__device__ float g_att[(size_t)TT * BB * 512];
__device__ __nv_bfloat16 g_ah[2097152], g_al[2097152];
__device__ __nv_bfloat16 g_wh[1310720], g_wl[1310720];

// ---------------------------------------------------------------------------
__global__ void k_sample_w(const float* __restrict__ mu, const float* __restrict__ rho,
                           const float* __restrict__ eps, float* __restrict__ w,
                           __nv_bfloat16* __restrict__ wh, __nv_bfloat16* __restrict__ wl) {
    int i = blockIdx.x * blockDim.x + threadIdx.x;
    if (i < N_W) {
        float r = rho[i];
        float sp = (r > 20.f) ? r : log1pf(expf(r));
        float v = fmaf(sp, eps[i], mu[i]);
        w[i] = v;
        if (i < 1310720) {
            __nv_bfloat16 h = __float2bfloat16(v);
            wh[i] = h;
            wl[i] = __float2bfloat16(v - __bfloat162float(h));
        }
    }
}

__global__ void k_split(const float* __restrict__ x, __nv_bfloat16* __restrict__ hi,
                        __nv_bfloat16* __restrict__ lo, int n) {
    int i = blockIdx.x * blockDim.x + threadIdx.x;
    if (i < n) {
        float v = x[i];
        __nv_bfloat16 h = __float2bfloat16(v);
        hi[i] = h;
        lo[i] = __float2bfloat16(v - __bfloat162float(h));
    }
}

// ---------------------------------------------------------------------------
// HMMA GEMM (proven): C = A @ W^T + bias, bf16 hi/lo 3-pass.
// ---------------------------------------------------------------------------
#define GS_AH 0
#define GS_AL 16384
#define GS_BH 32768
#define GS_BL 49152
#define SMEM_G 65536

__global__ __launch_bounds__(256, 2)
void k_hgemm(const __nv_bfloat16* __restrict__ Ah, const __nv_bfloat16* __restrict__ Al,
             const __nv_bfloat16* __restrict__ Wh, const __nv_bfloat16* __restrict__ Wl,
             const float* __restrict__ bias, float* __restrict__ C, int M, int N) {
    extern __shared__ char smem[];
    const u32 sb = s2u(smem);
    const int tid = threadIdx.x, lane = tid & 31, warp = tid >> 5;
    const int m0 = blockIdx.y * 128, n0 = blockIdx.x * 128;
    const int wm = (warp >> 2) * 64, wn = (warp & 3) * 32;
    const int rA = (lane & 7) + ((lane >> 3) & 1) * 8;
    const int cA = ((lane >> 4) & 1) * 16;
    const int rB = (lane & 7) + ((lane >> 4) & 1) * 8;
    const int cB = ((lane >> 3) & 1) * 16;

    float acc[4][4][4];
#pragma unroll
    for (int u = 0; u < 4; u++)
#pragma unroll
        for (int t = 0; t < 4; t++)
#pragma unroll
            for (int e = 0; e < 4; e++) acc[u][t][e] = 0.f;

    for (int c = 0; c < 8; c++) {
        __syncthreads();
#pragma unroll
        for (int p = 0; p < 4; p++) {
            int idx = p * 256 + tid;
            int row = idx >> 3, c8 = idx & 7;
            u32 off = swz(row * 128 + c8 * 16);
            size_t ga = (size_t)(m0 + row) * 512 + c * 64 + c8 * 8;
            size_t gb = (size_t)(n0 + row) * 512 + c * 64 + c8 * 8;
            *(uint4*)(smem + GS_AH + off) = *(const uint4*)(Ah + ga);
            *(uint4*)(smem + GS_AL + off) = *(const uint4*)(Al + ga);
            *(uint4*)(smem + GS_BH + off) = *(const uint4*)(Wh + gb);
            *(uint4*)(smem + GS_BL + off) = *(const uint4*)(Wl + gb);
        }
        __syncthreads();
#pragma unroll
        for (int s = 0; s < 4; s++) {
            u32 ah[4][4], al[4][4];
#pragma unroll
            for (int u = 0; u < 4; u++) {
                u32 off = swz((wm + u * 16 + rA) * 128 + cA + s * 32);
                ldm4(ah[u], sb + GS_AH + off);
                ldm4(al[u], sb + GS_AL + off);
            }
#pragma unroll
            for (int t = 0; t < 2; t++) {
                u32 bh[4], bl[4];
                u32 off = swz((wn + t * 16 + rB) * 128 + cB + s * 32);
                ldm4(bh, sb + GS_BH + off);
                ldm4(bl, sb + GS_BL + off);
#pragma unroll
                for (int h = 0; h < 2; h++) {
                    int n8 = t * 2 + h;
#pragma unroll
                    for (int u = 0; u < 4; u++) {
                        mma_bf16(acc[u][n8], ah[u], bh[2 * h], bh[2 * h + 1]);
                        mma_bf16(acc[u][n8], ah[u], bl[2 * h], bl[2 * h + 1]);
                        mma_bf16(acc[u][n8], al[u], bh[2 * h], bh[2 * h + 1]);
                    }
                }
            }
        }
    }
#pragma unroll
    for (int u = 0; u < 4; u++)
#pragma unroll
        for (int n8 = 0; n8 < 4; n8++) {
            int col = n0 + wn + n8 * 8 + 2 * (lane & 3);
            int row = m0 + wm + u * 16 + (lane >> 2);
            float2 bv = *(const float2*)(bias + col);
            *(float2*)(C + (size_t)row * N + col) =
                make_float2(acc[u][n8][0] + bv.x, acc[u][n8][1] + bv.y);
            *(float2*)(C + (size_t)(row + 8) * N + col) =
                make_float2(acc[u][n8][2] + bv.x, acc[u][n8][3] + bv.y);
        }
}

// ---------------------------------------------------------------------------
// Tensor-core flash attention with fused rel-shift + FMA-pipe softmax exp.
// ---------------------------------------------------------------------------
#define TF_QWH 0
#define TF_QWL 8192
#define TF_KH  16384
#define TF_KL  24576
#define TF_VH  32768
#define TF_VL  40960
#define TF_RH  49152
#define TF_RL  65536
#define TF_PH  81920
#define TF_PL  90112
#define TF_S   98304
#define TF_SC  148480
#define TF_LI  148736
#define TF_CO  148992
#define TF_DL  149504
#define TF_TOT 149760

__global__ __launch_bounds__(256)
void k_tflash(const float* __restrict__ qkv, const float* __restrict__ rbuf,
              const float* __restrict__ w, float* __restrict__ att) {
    extern __shared__ char smem[];
    float* Sb    = (float*)(smem + TF_S);     // [64][196]
    float* scale = (float*)(smem + TF_SC);
    float* linv  = (float*)(smem + TF_LI);
    float* corr  = (float*)(smem + TF_CO);
    float* delta = (float*)(smem + TF_DL);
    const u32 sb = s2u(smem);
    const int combo = blockIdx.x, b = combo >> 3, n = combo & 7;
    const int it = 31 - (int)blockIdx.y, i0 = it * 64;
    const int tid = threadIdx.x, lane = tid & 31, warp = tid >> 5;
    const int rA = (lane & 7) + ((lane >> 3) & 1) * 8;
    const int cA = ((lane >> 4) & 1) * 16;
    const int rB = (lane & 7) + ((lane >> 4) & 1) * 8;
    const int cB = ((lane >> 3) & 1) * 16;
    const int mi2 = (warp >> 2) * 32;
    const int nc0 = (warp & 3) * 48;
    const int d0 = (warp & 3) * 16;
    const int si = tid >> 2, jg = tid & 3;

    if (tid < 64)
        delta[tid] = w[OFF_RRB + n * 64 + tid] - w[OFF_RWB + n * 64 + tid];

#pragma unroll
    for (int p = 0; p < 2; p++) {
        int c = p * 256 + tid;
        int row = c >> 3, c8 = (c & 7) * 8;
        const float* qg = qkv + ((size_t)(i0 + row) * BB + b) * 1536 + n * 64 + c8;
        const float* bg = w + OFF_RWB + n * 64 + c8;
        float4 a = *(const float4*)qg, a2 = *(const float4*)(qg + 4);
        float4 bw = *(const float4*)bg, bw2 = *(const float4*)(bg + 4);
        a.x += bw.x; a.y += bw.y; a.z += bw.z; a.w += bw.w;
        a2.x += bw2.x; a2.y += bw2.y; a2.z += bw2.z; a2.w += bw2.w;
        uint4 h, l; cvt8(a, a2, h, l);
        u32 off = swz(row * 128 + c8 * 2);
        *(uint4*)(smem + TF_QWH + off) = h;
        *(uint4*)(smem + TF_QWL + off) = l;
    }

    float mrun = -1e30f, lrun = 0.f;
    float o[2][2][4];
#pragma unroll
    for (int u = 0; u < 2; u++)
#pragma unroll
        for (int h = 0; h < 2; h++)
#pragma unroll
            for (int e = 0; e < 4; e++) o[u][h][e] = 0.f;

    for (int jt = 0; jt <= it; jt++) {
        const int j0 = jt * 64;
        __syncthreads();
#pragma unroll
        for (int p = 0; p < 2; p++) {
            int c = p * 256 + tid;
            int row = c >> 3, c8 = (c & 7) * 8;
            const float* g = qkv + ((size_t)(j0 + row) * BB + b) * 1536 + n * 64 + c8;
            uint4 h, l;
            u32 off = swz(row * 128 + c8 * 2);
            cvt8(*(const float4*)(g + 512), *(const float4*)(g + 516), h, l);
            *(uint4*)(smem + TF_KH + off) = h;
            *(uint4*)(smem + TF_KL + off) = l;
            cvt8(*(const float4*)(g + 1024), *(const float4*)(g + 1028), h, l);
            *(uint4*)(smem + TF_VH + off) = h;
            *(uint4*)(smem + TF_VL + off) = l;
        }
        const int m_base = j0 - i0 + 1984;
#pragma unroll
        for (int p = 0; p < 4; p++) {
            int c = p * 256 + tid;
            int dd = c >> 3, c8 = (c & 7) * 8;
            int gm = m_base + dd;
            float4 ra = make_float4(0.f, 0.f, 0.f, 0.f), ra2 = ra;
            if (dd < 127 && gm < TT) {
                const float* g = rbuf + (size_t)gm * 512 + n * 64 + c8;
                ra = *(const float4*)g; ra2 = *(const float4*)(g + 4);
            }
            uint4 h, l; cvt8(ra, ra2, h, l);
            u32 off = swz(dd * 128 + c8 * 2);
            *(uint4*)(smem + TF_RH + off) = h;
            *(uint4*)(smem + TF_RL + off) = l;
        }
        if (tid < 127) {
            int gm = m_base + tid;
            float s = 0.f;
            if (gm < TT) {
                const float4* rr = (const float4*)(rbuf + (size_t)gm * 512 + n * 64);
                const float4* dl = (const float4*)delta;
#pragma unroll
                for (int k4 = 0; k4 < 16; k4++) {
                    float4 rv = rr[k4], dv = dl[k4];
                    s = fmaf(dv.x, rv.x, s); s = fmaf(dv.y, rv.y, s);
                    s = fmaf(dv.z, rv.z, s); s = fmaf(dv.w, rv.w, s);
                }
            }
            corr[tid] = s;
        }
        __syncthreads();

        // ---- S GEMM ----
        float c48[2][6][4];
#pragma unroll
        for (int u = 0; u < 2; u++)
#pragma unroll
            for (int t = 0; t < 6; t++)
#pragma unroll
                for (int e = 0; e < 4; e++) c48[u][t][e] = 0.f;
#pragma unroll
        for (int kk = 0; kk < 4; kk++) {
            u32 ah[2][4], al[2][4];
#pragma unroll
            for (int u = 0; u < 2; u++) {
                u32 off = swz((mi2 + u * 16 + rA) * 128 + cA + kk * 32);
                ldm4(ah[u], sb + TF_QWH + off);
                ldm4(al[u], sb + TF_QWL + off);
            }
#pragma unroll
            for (int nt = 0; nt < 3; nt++) {
                int col0 = nc0 + nt * 16;
                u32 bufh = (col0 < 64) ? TF_KH : TF_RH;
                u32 bufl = (col0 < 64) ? TF_KL : TF_RL;
                int brow = (col0 < 64) ? col0 : col0 - 64;
                u32 bh[4], bl[4];
                u32 off = swz((brow + rB) * 128 + cB + kk * 32);
                ldm4(bh, sb + bufh + off);
                ldm4(bl, sb + bufl + off);
#pragma unroll
                for (int u = 0; u < 2; u++)
#pragma unroll
                    for (int h = 0; h < 2; h++) {
                        float* cc = c48[u][nt * 2 + h];
                        mma_bf16(cc, ah[u], bh[2 * h], bh[2 * h + 1]);
                        mma_bf16(cc, ah[u], bl[2 * h], bl[2 * h + 1]);
                        mma_bf16(cc, al[u], bh[2 * h], bh[2 * h + 1]);
                    }
            }
        }
#pragma unroll
        for (int u = 0; u < 2; u++)
#pragma unroll
            for (int t = 0; t < 6; t++) {
                int row = mi2 + u * 16 + (lane >> 2);
                int col = nc0 + t * 8 + (lane & 3) * 2;
                *(float2*)&Sb[row * 196 + col] = make_float2(c48[u][t][0], c48[u][t][1]);
                *(float2*)&Sb[(row + 8) * 196 + col] = make_float2(c48[u][t][2], c48[u][t][3]);
            }
        __syncthreads();

        // ---- softmax (FMA-pipe exp) ----
        {
            float pv[16];
            float mloc = -1e30f;
            const float* srow = Sb + si * 196;
#pragma unroll
            for (int jj = 0; jj < 16; jj++) {
                int j = jg * 16 + jj;
                float v = -1e30f;
                if (jt < it || j <= si) {
                    int dd = j - si + 63;
                    v = 0.125f * (srow[j] + srow[64 + dd] + corr[dd]);
                }
                pv[jj] = v;
                mloc = fmaxf(mloc, v);
            }
            mloc = fmaxf(mloc, __shfl_xor_sync(0xffffffffu, mloc, 1));
            mloc = fmaxf(mloc, __shfl_xor_sync(0xffffffffu, mloc, 2));
            float mnew = fmaxf(mrun, mloc);
            float sc = __expf(mrun - mnew);
            mrun = mnew;
            float ls = 0.f;
            u32 hb[8], lb[8];
#pragma unroll
            for (int q = 0; q < 8; q++) {
                float y0 = fmaxf(pv[2 * q] - mnew, -80.f);
                float y1 = fmaxf(pv[2 * q + 1] - mnew, -80.f);
                float p0, p1;
                exp2pair(y0, y1, p0, p1);
                ls += p0 + p1;
                hl2(p0, p1, hb[q], lb[q]);
            }
            ls += __shfl_xor_sync(0xffffffffu, ls, 1);
            ls += __shfl_xor_sync(0xffffffffu, ls, 2);
            lrun = lrun * sc + ls;
            if ((tid & 3) == 0) scale[si] = sc;
            u32 off0 = swz(si * 128 + jg * 32), off1 = swz(si * 128 + jg * 32 + 16);
            *(uint4*)(smem + TF_PH + off0) = make_uint4(hb[0], hb[1], hb[2], hb[3]);
            *(uint4*)(smem + TF_PH + off1) = make_uint4(hb[4], hb[5], hb[6], hb[7]);
            *(uint4*)(smem + TF_PL + off0) = make_uint4(lb[0], lb[1], lb[2], lb[3]);
            *(uint4*)(smem + TF_PL + off1) = make_uint4(lb[4], lb[5], lb[6], lb[7]);
        }
        __syncthreads();

        // ---- PV ----
#pragma unroll
        for (int u = 0; u < 2; u++) {
            float sA_ = scale[mi2 + u * 16 + (lane >> 2)];
            float sB_ = scale[mi2 + u * 16 + 8 + (lane >> 2)];
#pragma unroll
            for (int h = 0; h < 2; h++) {
                o[u][h][0] *= sA_; o[u][h][1] *= sA_;
                o[u][h][2] *= sB_; o[u][h][3] *= sB_;
            }
        }
#pragma unroll
        for (int kk = 0; kk < 4; kk++) {
            u32 ph[2][4], pl[2][4];
#pragma unroll
            for (int u = 0; u < 2; u++) {
                u32 off = swz((mi2 + u * 16 + rA) * 128 + cA + kk * 32);
                ldm4(ph[u], sb + TF_PH + off);
                ldm4(pl[u], sb + TF_PL + off);
            }
            u32 vh[4], vl[4];
            u32 vo = swz((kk * 16 + rA) * 128 + d0 * 2 + cA);
            ldm4t(vh, sb + TF_VH + vo);
            ldm4t(vl, sb + TF_VL + vo);
#pragma unroll
            for (int u = 0; u < 2; u++)
#pragma unroll
                for (int h = 0; h < 2; h++) {
                    mma_bf16(o[u][h], ph[u], vh[2 * h], vh[2 * h + 1]);
                    mma_bf16(o[u][h], ph[u], vl[2 * h], vl[2 * h + 1]);
                    mma_bf16(o[u][h], pl[u], vh[2 * h], vh[2 * h + 1]);
                }
        }
    }

    if ((tid & 3) == 0) linv[si] = 1.f / lrun;
    __syncthreads();
#pragma unroll
    for (int u = 0; u < 2; u++) {
        int r0 = mi2 + u * 16 + (lane >> 2);
        float i0v = linv[r0], i1v = linv[r0 + 8];
#pragma unroll
        for (int h = 0; h < 2; h++) {
            int col = d0 + h * 8 + (lane & 3) * 2;
            *(float2*)(att + ((size_t)(i0 + r0) * BB + b) * 512 + n * 64 + col) =
                make_float2(o[u][h][0] * i0v, o[u][h][1] * i0v);
            *(float2*)(att + ((size_t)(i0 + r0 + 8) * BB + b) * 512 + n * 64 + col) =
                make_float2(o[u][h][2] * i1v, o[u][h][3] * i1v);
        }
    }
}

// ---------------------------------------------------------------------------
extern "C" void kernel_launch(void* const* d_in, const int* in_sizes, int n_in,
                              void* d_out, int out_size) {
    const float* input = (const float*)d_in[0];
    const float* pos   = (const float*)d_in[1];
    const float* mu    = (const float*)d_in[3];
    const float* rho   = (const float*)d_in[4];
    const float* eps   = (const float*)d_in[5];
    float* out = (float*)d_out;

    float *w, *qkv, *r, *att;
    __nv_bfloat16 *ah, *al, *wh, *wl;
    cudaGetSymbolAddress((void**)&w,   g_w);
    cudaGetSymbolAddress((void**)&qkv, g_qkv);
    cudaGetSymbolAddress((void**)&r,   g_r);
    cudaGetSymbolAddress((void**)&att, g_att);
    cudaGetSymbolAddress((void**)&ah,  g_ah);
    cudaGetSymbolAddress((void**)&al,  g_al);
    cudaGetSymbolAddress((void**)&wh,  g_wh);
    cudaGetSymbolAddress((void**)&wl,  g_wl);

    static bool attr_set = false;
    if (!attr_set) {
        cudaFuncSetAttribute(k_hgemm, cudaFuncAttributeMaxDynamicSharedMemorySize, SMEM_G);
        cudaFuncSetAttribute(k_tflash, cudaFuncAttributeMaxDynamicSharedMemorySize, TF_TOT);
        attr_set = true;
    }

    k_sample_w<<<(N_W + 255) / 256, 256>>>(mu, rho, eps, w, wh, wl);

    k_split<<<(2097152 + 255) / 256, 256>>>(input, ah, al, 2097152);
    k_hgemm<<<dim3(12, 32), 256, SMEM_G>>>(ah, al, wh + OFF_INW, wl + OFF_INW,
                                           w + OFF_INB, qkv, 4096, 1536);
    k_split<<<(1048576 + 255) / 256, 256>>>(pos, ah, al, 1048576);
    k_hgemm<<<dim3(4, 16), 256, SMEM_G>>>(ah, al, wh + OFF_POSW, wl + OFF_POSW,
                                          w + OFF_POSB, r, 2048, 512);

    k_tflash<<<dim3(BB * NHH, 32), 256, TF_TOT>>>(qkv, r, w, att);

    k_split<<<(2097152 + 255) / 256, 256>>>(att, ah, al, 2097152);
    k_hgemm<<<dim3(4, 32), 256, SMEM_G>>>(ah, al, wh + OFF_OUTW, wl + OFF_OUTW,
                                          w + OFF_OUTB, out, 4096, 512);
}

// round 14
// speedup vs baseline: 1.0397x; 1.0397x over previous
#include <cuda_runtime.h>
#include <cuda_bf16.h>
#include <cstdint>
#include <math.h>

#define TT  2048
#define BB  2
#define NHH 8

#define OFF_INW   0
#define OFF_OUTW  786432
#define OFF_POSW  1048576
#define OFF_INB   1310720
#define OFF_OUTB  1312256
#define OFF_POSB  1312768
#define OFF_RWB   1313280
#define OFF_RRB   1313792
#define N_W       1314304

typedef unsigned long long u64;
typedef unsigned int u32;

__device__ __forceinline__ u32 s2u(const void* p) {
    u32 a;
    asm("{.reg .u64 t; cvta.to.shared.u64 t, %1; cvt.u32.u64 %0, t;}" : "=r"(a) : "l"(p));
    return a;
}
__device__ __forceinline__ void ldm4(u32* r, u32 addr) {
    asm volatile("ldmatrix.sync.aligned.m8n8.x4.shared.b16 {%0,%1,%2,%3}, [%4];"
        : "=r"(r[0]), "=r"(r[1]), "=r"(r[2]), "=r"(r[3]) : "r"(addr));
}
__device__ __forceinline__ void ldm4t(u32* r, u32 addr) {
    asm volatile("ldmatrix.sync.aligned.m8n8.x4.trans.shared.b16 {%0,%1,%2,%3}, [%4];"
        : "=r"(r[0]), "=r"(r[1]), "=r"(r[2]), "=r"(r[3]) : "r"(addr));
}
__device__ __forceinline__ void mma_bf16(float* c, const u32* a, u32 b0, u32 b1) {
    asm volatile("mma.sync.aligned.m16n8k16.row.col.f32.bf16.bf16.f32 "
        "{%0,%1,%2,%3}, {%4,%5,%6,%7}, {%8,%9}, {%0,%1,%2,%3};"
        : "+f"(c[0]), "+f"(c[1]), "+f"(c[2]), "+f"(c[3])
        : "r"(a[0]), "r"(a[1]), "r"(a[2]), "r"(a[3]), "r"(b0), "r"(b1));
}
__device__ __forceinline__ u32 swz(u32 b) { return b ^ ((b >> 3) & 0x70); }

__device__ __forceinline__ u64 pk2(float lo, float hi) {
    u64 r; asm("mov.b64 %0, {%1, %2};" : "=l"(r) : "f"(lo), "f"(hi)); return r;
}
__device__ __forceinline__ u64 splat2(float x) {
    u64 r; asm("mov.b64 %0, {%1, %1};" : "=l"(r) : "f"(x)); return r;
}
__device__ __forceinline__ u64 ffma2(u64 a, u64 b, u64 c) {
    u64 d; asm("fma.rn.f32x2 %0, %1, %2, %3;" : "=l"(d) : "l"(a), "l"(b), "l"(c));
    return d;
}
__device__ __forceinline__ void upk2u(u64 v, u32& lo, u32& hi) {
    asm("mov.b64 {%0, %1}, %2;" : "=r"(lo), "=r"(hi) : "l"(v));
}

// packed exp(y0), exp(y1) for y in [-87, 0] (exact pre-subtracted inputs).
__device__ __forceinline__ void exp2pair(float y0, float y1, float& e0, float& e1) {
    const u64 L2E2 = splat2(1.44269504088896f);
    const u64 MAGIC = splat2(12582912.0f);
    u64 y2 = pk2(y0, y1);
    u64 t2 = ffma2(y2, L2E2, MAGIC);
    u64 s2 = ffma2(t2, splat2(-1.f), MAGIC);
    u64 f2 = ffma2(y2, L2E2, s2);
    u64 p2 = ffma2(f2, splat2(1.3333558e-3f), splat2(9.6181291e-3f));
    p2 = ffma2(f2, p2, splat2(5.5504109e-2f));
    p2 = ffma2(f2, p2, splat2(2.4022651e-1f));
    p2 = ffma2(f2, p2, splat2(6.9314718e-1f));
    p2 = ffma2(f2, p2, splat2(1.0f));
    u32 tl, th, pl, ph;
    upk2u(t2, tl, th);
    upk2u(p2, pl, ph);
    e0 = __uint_as_float(pl + (tl << 23));
    e1 = __uint_as_float(ph + (th << 23));
}

__device__ __forceinline__ void hl2(float x, float y, u32& h, u32& l) {
    __nv_bfloat16 hx = __float2bfloat16(x), hy = __float2bfloat16(y);
    __nv_bfloat16 lx = __float2bfloat16(x - __bfloat162float(hx));
    __nv_bfloat16 ly = __float2bfloat16(y - __bfloat162float(hy));
    __nv_bfloat162 hh = __halves2bfloat162(hx, hy), ll = __halves2bfloat162(lx, ly);
    h = *(u32*)&hh; l = *(u32*)&ll;
}
__device__ __forceinline__ void cvt8(float4 a, float4 b2, uint4& h, uint4& l) {
    hl2(a.x, a.y, h.x, l.x); hl2(a.z, a.w, h.y, l.y);
    hl2(b2.x, b2.y, h.z, l.z); hl2(b2.z, b2.w, h.w, l.w);
}

__device__ float g_w[N_W];
__device__ float g_qkv[(size_t)TT * BB * 3 * 512];
__device__ float g_r[(size_t)TT * 512];
__device__ float g_att[(size_t)TT * BB * 512];
__device__ __nv_bfloat16 g_ah[2097152], g_al[2097152];
__device__ __nv_bfloat16 g_wh[1310720], g_wl[1310720];

// ---------------------------------------------------------------------------
__global__ void k_sample_w(const float* __restrict__ mu, const float* __restrict__ rho,
                           const float* __restrict__ eps, float* __restrict__ w,
                           __nv_bfloat16* __restrict__ wh, __nv_bfloat16* __restrict__ wl) {
    int i = blockIdx.x * blockDim.x + threadIdx.x;
    if (i < N_W) {
        float r = rho[i];
        float sp = (r > 20.f) ? r : log1pf(expf(r));
        float v = fmaf(sp, eps[i], mu[i]);
        w[i] = v;
        if (i < 1310720) {
            __nv_bfloat16 h = __float2bfloat16(v);
            wh[i] = h;
            wl[i] = __float2bfloat16(v - __bfloat162float(h));
        }
    }
}

__global__ void k_split(const float* __restrict__ x, __nv_bfloat16* __restrict__ hi,
                        __nv_bfloat16* __restrict__ lo, int n) {
    int i = blockIdx.x * blockDim.x + threadIdx.x;
    if (i < n) {
        float v = x[i];
        __nv_bfloat16 h = __float2bfloat16(v);
        hi[i] = h;
        lo[i] = __float2bfloat16(v - __bfloat162float(h));
    }
}

// ---------------------------------------------------------------------------
// HMMA GEMM (proven): C = A @ W^T + bias, bf16 hi/lo 3-pass.
// ---------------------------------------------------------------------------
#define GS_AH 0
#define GS_AL 16384
#define GS_BH 32768
#define GS_BL 49152
#define SMEM_G 65536

__global__ __launch_bounds__(256, 2)
void k_hgemm(const __nv_bfloat16* __restrict__ Ah, const __nv_bfloat16* __restrict__ Al,
             const __nv_bfloat16* __restrict__ Wh, const __nv_bfloat16* __restrict__ Wl,
             const float* __restrict__ bias, float* __restrict__ C, int M, int N) {
    extern __shared__ char smem[];
    const u32 sb = s2u(smem);
    const int tid = threadIdx.x, lane = tid & 31, warp = tid >> 5;
    const int m0 = blockIdx.y * 128, n0 = blockIdx.x * 128;
    const int wm = (warp >> 2) * 64, wn = (warp & 3) * 32;
    const int rA = (lane & 7) + ((lane >> 3) & 1) * 8;
    const int cA = ((lane >> 4) & 1) * 16;
    const int rB = (lane & 7) + ((lane >> 4) & 1) * 8;
    const int cB = ((lane >> 3) & 1) * 16;

    float acc[4][4][4];
#pragma unroll
    for (int u = 0; u < 4; u++)
#pragma unroll
        for (int t = 0; t < 4; t++)
#pragma unroll
            for (int e = 0; e < 4; e++) acc[u][t][e] = 0.f;

    for (int c = 0; c < 8; c++) {
        __syncthreads();
#pragma unroll
        for (int p = 0; p < 4; p++) {
            int idx = p * 256 + tid;
            int row = idx >> 3, c8 = idx & 7;
            u32 off = swz(row * 128 + c8 * 16);
            size_t ga = (size_t)(m0 + row) * 512 + c * 64 + c8 * 8;
            size_t gb = (size_t)(n0 + row) * 512 + c * 64 + c8 * 8;
            *(uint4*)(smem + GS_AH + off) = *(const uint4*)(Ah + ga);
            *(uint4*)(smem + GS_AL + off) = *(const uint4*)(Al + ga);
            *(uint4*)(smem + GS_BH + off) = *(const uint4*)(Wh + gb);
            *(uint4*)(smem + GS_BL + off) = *(const uint4*)(Wl + gb);
        }
        __syncthreads();
#pragma unroll
        for (int s = 0; s < 4; s++) {
            u32 ah[4][4], al[4][4];
#pragma unroll
            for (int u = 0; u < 4; u++) {
                u32 off = swz((wm + u * 16 + rA) * 128 + cA + s * 32);
                ldm4(ah[u], sb + GS_AH + off);
                ldm4(al[u], sb + GS_AL + off);
            }
#pragma unroll
            for (int t = 0; t < 2; t++) {
                u32 bh[4], bl[4];
                u32 off = swz((wn + t * 16 + rB) * 128 + cB + s * 32);
                ldm4(bh, sb + GS_BH + off);
                ldm4(bl, sb + GS_BL + off);
#pragma unroll
                for (int h = 0; h < 2; h++) {
                    int n8 = t * 2 + h;
#pragma unroll
                    for (int u = 0; u < 4; u++) {
                        mma_bf16(acc[u][n8], ah[u], bh[2 * h], bh[2 * h + 1]);
                        mma_bf16(acc[u][n8], ah[u], bl[2 * h], bl[2 * h + 1]);
                        mma_bf16(acc[u][n8], al[u], bh[2 * h], bh[2 * h + 1]);
                    }
                }
            }
        }
    }
#pragma unroll
    for (int u = 0; u < 4; u++)
#pragma unroll
        for (int n8 = 0; n8 < 4; n8++) {
            int col = n0 + wn + n8 * 8 + 2 * (lane & 3);
            int row = m0 + wm + u * 16 + (lane >> 2);
            float2 bv = *(const float2*)(bias + col);
            *(float2*)(C + (size_t)row * N + col) =
                make_float2(acc[u][n8][0] + bv.x, acc[u][n8][1] + bv.y);
            *(float2*)(C + (size_t)(row + 8) * N + col) =
                make_float2(acc[u][n8][2] + bv.x, acc[u][n8][3] + bv.y);
        }
}

// ---------------------------------------------------------------------------
// Tensor-core flash attention, rel-shift fused. Sb ALIASED over K+R region
// (dead after S GEMM) -> 97.3 KB smem -> 2 CTAs/SM.
// Sb: 64 rows x 191 cols fp32 (cols 0..63 = S1, 64+dd dd in [0,126] = S2).
// ---------------------------------------------------------------------------
#define TF_QWH 0
#define TF_QWL 8192
#define TF_KH  16384
#define TF_KL  24576
#define TF_RH  32768
#define TF_RL  49152
#define TF_VH  65536
#define TF_VL  73728
#define TF_PH  81920
#define TF_PL  90112
#define TF_SC  98304
#define TF_LI  98560
#define TF_CO  98816
#define TF_DL  99328
#define TF_TOT 99584

__global__ __launch_bounds__(256, 2)
void k_tflash(const float* __restrict__ qkv, const float* __restrict__ rbuf,
              const float* __restrict__ w, float* __restrict__ att) {
    extern __shared__ char smem[];
    float* Sb    = (float*)(smem + TF_KH);    // aliased over KH..RL, [64][191]
    float* scale = (float*)(smem + TF_SC);
    float* linv  = (float*)(smem + TF_LI);
    float* corr  = (float*)(smem + TF_CO);
    float* delta = (float*)(smem + TF_DL);
    const u32 sb = s2u(smem);
    const int combo = blockIdx.x, b = combo >> 3, n = combo & 7;
    const int it = 31 - (int)blockIdx.y, i0 = it * 64;
    const int tid = threadIdx.x, lane = tid & 31, warp = tid >> 5;
    const int rA = (lane & 7) + ((lane >> 3) & 1) * 8;
    const int cA = ((lane >> 4) & 1) * 16;
    const int rB = (lane & 7) + ((lane >> 4) & 1) * 8;
    const int cB = ((lane >> 3) & 1) * 16;
    const int mi2 = (warp >> 2) * 32;
    const int nc0 = (warp & 3) * 48;
    const int d0 = (warp & 3) * 16;
    const int si = tid >> 2, jg = tid & 3;

    if (tid < 64)
        delta[tid] = w[OFF_RRB + n * 64 + tid] - w[OFF_RWB + n * 64 + tid];

#pragma unroll
    for (int p = 0; p < 2; p++) {
        int c = p * 256 + tid;
        int row = c >> 3, c8 = (c & 7) * 8;
        const float* qg = qkv + ((size_t)(i0 + row) * BB + b) * 1536 + n * 64 + c8;
        const float* bg = w + OFF_RWB + n * 64 + c8;
        float4 a = *(const float4*)qg, a2 = *(const float4*)(qg + 4);
        float4 bw = *(const float4*)bg, bw2 = *(const float4*)(bg + 4);
        a.x += bw.x; a.y += bw.y; a.z += bw.z; a.w += bw.w;
        a2.x += bw2.x; a2.y += bw2.y; a2.z += bw2.z; a2.w += bw2.w;
        uint4 h, l; cvt8(a, a2, h, l);
        u32 off = swz(row * 128 + c8 * 2);
        *(uint4*)(smem + TF_QWH + off) = h;
        *(uint4*)(smem + TF_QWL + off) = l;
    }

    float mrun = -1e30f, lrun = 0.f;
    float o[2][2][4];
#pragma unroll
    for (int u = 0; u < 2; u++)
#pragma unroll
        for (int h = 0; h < 2; h++)
#pragma unroll
            for (int e = 0; e < 4; e++) o[u][h][e] = 0.f;

    for (int jt = 0; jt <= it; jt++) {
        const int j0 = jt * 64;
        __syncthreads();   // prev softmax Sb reads + prev PV V/P reads done
#pragma unroll
        for (int p = 0; p < 2; p++) {
            int c = p * 256 + tid;
            int row = c >> 3, c8 = (c & 7) * 8;
            const float* g = qkv + ((size_t)(j0 + row) * BB + b) * 1536 + n * 64 + c8;
            uint4 h, l;
            u32 off = swz(row * 128 + c8 * 2);
            cvt8(*(const float4*)(g + 512), *(const float4*)(g + 516), h, l);
            *(uint4*)(smem + TF_KH + off) = h;
            *(uint4*)(smem + TF_KL + off) = l;
            cvt8(*(const float4*)(g + 1024), *(const float4*)(g + 1028), h, l);
            *(uint4*)(smem + TF_VH + off) = h;
            *(uint4*)(smem + TF_VL + off) = l;
        }
        const int m_base = j0 - i0 + 1984;
#pragma unroll
        for (int p = 0; p < 4; p++) {
            int c = p * 256 + tid;
            int dd = c >> 3, c8 = (c & 7) * 8;
            int gm = m_base + dd;
            float4 ra = make_float4(0.f, 0.f, 0.f, 0.f), ra2 = ra;
            if (dd < 127 && gm < TT) {
                const float* g = rbuf + (size_t)gm * 512 + n * 64 + c8;
                ra = *(const float4*)g; ra2 = *(const float4*)(g + 4);
            }
            uint4 h, l; cvt8(ra, ra2, h, l);
            u32 off = swz(dd * 128 + c8 * 2);
            *(uint4*)(smem + TF_RH + off) = h;
            *(uint4*)(smem + TF_RL + off) = l;
        }
        if (tid < 127) {
            int gm = m_base + tid;
            float s = 0.f;
            if (gm < TT) {
                const float4* rr = (const float4*)(rbuf + (size_t)gm * 512 + n * 64);
                const float4* dl = (const float4*)delta;
#pragma unroll
                for (int k4 = 0; k4 < 16; k4++) {
                    float4 rv = rr[k4], dv = dl[k4];
                    s = fmaf(dv.x, rv.x, s); s = fmaf(dv.y, rv.y, s);
                    s = fmaf(dv.z, rv.z, s); s = fmaf(dv.w, rv.w, s);
                }
            }
            corr[tid] = s;
        }
        __syncthreads();

        // ---- S GEMM (reads QW, K, R) ----
        float c48[2][6][4];
#pragma unroll
        for (int u = 0; u < 2; u++)
#pragma unroll
            for (int t = 0; t < 6; t++)
#pragma unroll
                for (int e = 0; e < 4; e++) c48[u][t][e] = 0.f;
#pragma unroll
        for (int kk = 0; kk < 4; kk++) {
            u32 ah[2][4], al[2][4];
#pragma unroll
            for (int u = 0; u < 2; u++) {
                u32 off = swz((mi2 + u * 16 + rA) * 128 + cA + kk * 32);
                ldm4(ah[u], sb + TF_QWH + off);
                ldm4(al[u], sb + TF_QWL + off);
            }
#pragma unroll
            for (int nt = 0; nt < 3; nt++) {
                int col0 = nc0 + nt * 16;
                u32 bufh = (col0 < 64) ? TF_KH : TF_RH;
                u32 bufl = (col0 < 64) ? TF_KL : TF_RL;
                int brow = (col0 < 64) ? col0 : col0 - 64;
                u32 bh[4], bl[4];
                u32 off = swz((brow + rB) * 128 + cB + kk * 32);
                ldm4(bh, sb + bufh + off);
                ldm4(bl, sb + bufl + off);
#pragma unroll
                for (int u = 0; u < 2; u++)
#pragma unroll
                    for (int h = 0; h < 2; h++) {
                        float* cc = c48[u][nt * 2 + h];
                        mma_bf16(cc, ah[u], bh[2 * h], bh[2 * h + 1]);
                        mma_bf16(cc, ah[u], bl[2 * h], bl[2 * h + 1]);
                        mma_bf16(cc, al[u], bh[2 * h], bh[2 * h + 1]);
                    }
            }
        }
        __syncthreads();   // all K/R reads done before Sb alias writes

        // ---- S store (Sb aliases K/R; stride 191; drop col 191) ----
#pragma unroll
        for (int u = 0; u < 2; u++)
#pragma unroll
            for (int t = 0; t < 6; t++) {
                int row = mi2 + u * 16 + (lane >> 2);
                int col = nc0 + t * 8 + (lane & 3) * 2;
                Sb[row * 191 + col] = c48[u][t][0];
                Sb[(row + 8) * 191 + col] = c48[u][t][2];
                if (col < 190) {
                    Sb[row * 191 + col + 1] = c48[u][t][1];
                    Sb[(row + 8) * 191 + col + 1] = c48[u][t][3];
                }
            }
        __syncthreads();

        // ---- softmax (FMA-pipe exp) ----
        {
            float pv[16];
            float mloc = -1e30f;
            const float* srow = Sb + si * 191;
#pragma unroll
            for (int jj = 0; jj < 16; jj++) {
                int j = jg * 16 + jj;
                float v = -1e30f;
                if (jt < it || j <= si) {
                    int dd = j - si + 63;
                    v = 0.125f * (srow[j] + srow[64 + dd] + corr[dd]);
                }
                pv[jj] = v;
                mloc = fmaxf(mloc, v);
            }
            mloc = fmaxf(mloc, __shfl_xor_sync(0xffffffffu, mloc, 1));
            mloc = fmaxf(mloc, __shfl_xor_sync(0xffffffffu, mloc, 2));
            float mnew = fmaxf(mrun, mloc);
            float sc = __expf(mrun - mnew);
            mrun = mnew;
            float ls = 0.f;
            u32 hb[8], lb[8];
#pragma unroll
            for (int q = 0; q < 8; q++) {
                float y0 = fmaxf(pv[2 * q] - mnew, -80.f);
                float y1 = fmaxf(pv[2 * q + 1] - mnew, -80.f);
                float p0, p1;
                exp2pair(y0, y1, p0, p1);
                ls += p0 + p1;
                hl2(p0, p1, hb[q], lb[q]);
            }
            ls += __shfl_xor_sync(0xffffffffu, ls, 1);
            ls += __shfl_xor_sync(0xffffffffu, ls, 2);
            lrun = lrun * sc + ls;
            if ((tid & 3) == 0) scale[si] = sc;
            u32 off0 = swz(si * 128 + jg * 32), off1 = swz(si * 128 + jg * 32 + 16);
            *(uint4*)(smem + TF_PH + off0) = make_uint4(hb[0], hb[1], hb[2], hb[3]);
            *(uint4*)(smem + TF_PH + off1) = make_uint4(hb[4], hb[5], hb[6], hb[7]);
            *(uint4*)(smem + TF_PL + off0) = make_uint4(lb[0], lb[1], lb[2], lb[3]);
            *(uint4*)(smem + TF_PL + off1) = make_uint4(lb[4], lb[5], lb[6], lb[7]);
        }
        __syncthreads();

        // ---- PV ----
#pragma unroll
        for (int u = 0; u < 2; u++) {
            float sA_ = scale[mi2 + u * 16 + (lane >> 2)];
            float sB_ = scale[mi2 + u * 16 + 8 + (lane >> 2)];
#pragma unroll
            for (int h = 0; h < 2; h++) {
                o[u][h][0] *= sA_; o[u][h][1] *= sA_;
                o[u][h][2] *= sB_; o[u][h][3] *= sB_;
            }
        }
#pragma unroll
        for (int kk = 0; kk < 4; kk++) {
            u32 ph[2][4], pl[2][4];
#pragma unroll
            for (int u = 0; u < 2; u++) {
                u32 off = swz((mi2 + u * 16 + rA) * 128 + cA + kk * 32);
                ldm4(ph[u], sb + TF_PH + off);
                ldm4(pl[u], sb + TF_PL + off);
            }
            u32 vh[4], vl[4];
            u32 vo = swz((kk * 16 + rA) * 128 + d0 * 2 + cA);
            ldm4t(vh, sb + TF_VH + vo);
            ldm4t(vl, sb + TF_VL + vo);
#pragma unroll
            for (int u = 0; u < 2; u++)
#pragma unroll
                for (int h = 0; h < 2; h++) {
                    mma_bf16(o[u][h], ph[u], vh[2 * h], vh[2 * h + 1]);
                    mma_bf16(o[u][h], ph[u], vl[2 * h], vl[2 * h + 1]);
                    mma_bf16(o[u][h], pl[u], vh[2 * h], vh[2 * h + 1]);
                }
        }
    }

    if ((tid & 3) == 0) linv[si] = 1.f / lrun;
    __syncthreads();
#pragma unroll
    for (int u = 0; u < 2; u++) {
        int r0 = mi2 + u * 16 + (lane >> 2);
        float i0v = linv[r0], i1v = linv[r0 + 8];
#pragma unroll
        for (int h = 0; h < 2; h++) {
            int col = d0 + h * 8 + (lane & 3) * 2;
            *(float2*)(att + ((size_t)(i0 + r0) * BB + b) * 512 + n * 64 + col) =
                make_float2(o[u][h][0] * i0v, o[u][h][1] * i0v);
            *(float2*)(att + ((size_t)(i0 + r0 + 8) * BB + b) * 512 + n * 64 + col) =
                make_float2(o[u][h][2] * i1v, o[u][h][3] * i1v);
        }
    }
}

// ---------------------------------------------------------------------------
extern "C" void kernel_launch(void* const* d_in, const int* in_sizes, int n_in,
                              void* d_out, int out_size) {
    const float* input = (const float*)d_in[0];
    const float* pos   = (const float*)d_in[1];
    const float* mu    = (const float*)d_in[3];
    const float* rho   = (const float*)d_in[4];
    const float* eps   = (const float*)d_in[5];
    float* out = (float*)d_out;

    float *w, *qkv, *r, *att;
    __nv_bfloat16 *ah, *al, *wh, *wl;
    cudaGetSymbolAddress((void**)&w,   g_w);
    cudaGetSymbolAddress((void**)&qkv, g_qkv);
    cudaGetSymbolAddress((void**)&r,   g_r);
    cudaGetSymbolAddress((void**)&att, g_att);
    cudaGetSymbolAddress((void**)&ah,  g_ah);
    cudaGetSymbolAddress((void**)&al,  g_al);
    cudaGetSymbolAddress((void**)&wh,  g_wh);
    cudaGetSymbolAddress((void**)&wl,  g_wl);

    static bool attr_set = false;
    if (!attr_set) {
        cudaFuncSetAttribute(k_hgemm, cudaFuncAttributeMaxDynamicSharedMemorySize, SMEM_G);
        cudaFuncSetAttribute(k_tflash, cudaFuncAttributeMaxDynamicSharedMemorySize, TF_TOT);
        attr_set = true;
    }

    k_sample_w<<<(N_W + 255) / 256, 256>>>(mu, rho, eps, w, wh, wl);

    k_split<<<(2097152 + 255) / 256, 256>>>(input, ah, al, 2097152);
    k_hgemm<<<dim3(12, 32), 256, SMEM_G>>>(ah, al, wh + OFF_INW, wl + OFF_INW,
                                           w + OFF_INB, qkv, 4096, 1536);
    k_split<<<(1048576 + 255) / 256, 256>>>(pos, ah, al, 1048576);
    k_hgemm<<<dim3(4, 16), 256, SMEM_G>>>(ah, al, wh + OFF_POSW, wl + OFF_POSW,
                                          w + OFF_POSB, r, 2048, 512);

    k_tflash<<<dim3(BB * NHH, 32), 256, TF_TOT>>>(qkv, r, w, att);

    k_split<<<(2097152 + 255) / 256, 256>>>(att, ah, al, 2097152);
    k_hgemm<<<dim3(4, 32), 256, SMEM_G>>>(ah, al, wh + OFF_OUTW, wl + OFF_OUTW,
                                          w + OFF_OUTB, out, 4096, 512);
}

// round 15
// speedup vs baseline: 1.1451x; 1.1014x over previous
#include <cuda_runtime.h>
#include <cuda_bf16.h>
#include <cstdint>
#include <math.h>

#define TT  2048
#define BB  2
#define NHH 8

#define OFF_INW   0
#define OFF_OUTW  786432
#define OFF_POSW  1048576
#define OFF_INB   1310720
#define OFF_OUTB  1312256
#define OFF_POSB  1312768
#define OFF_RWB   1313280
#define OFF_RRB   1313792
#define N_W       1314304

typedef unsigned long long u64;
typedef unsigned int u32;

__device__ __forceinline__ u32 s2u(const void* p) {
    u32 a;
    asm("{.reg .u64 t; cvta.to.shared.u64 t, %1; cvt.u32.u64 %0, t;}" : "=r"(a) : "l"(p));
    return a;
}
__device__ __forceinline__ void ldm4(u32* r, u32 addr) {
    asm volatile("ldmatrix.sync.aligned.m8n8.x4.shared.b16 {%0,%1,%2,%3}, [%4];"
        : "=r"(r[0]), "=r"(r[1]), "=r"(r[2]), "=r"(r[3]) : "r"(addr));
}
__device__ __forceinline__ void ldm4t(u32* r, u32 addr) {
    asm volatile("ldmatrix.sync.aligned.m8n8.x4.trans.shared.b16 {%0,%1,%2,%3}, [%4];"
        : "=r"(r[0]), "=r"(r[1]), "=r"(r[2]), "=r"(r[3]) : "r"(addr));
}
__device__ __forceinline__ void mma_bf16(float* c, const u32* a, u32 b0, u32 b1) {
    asm volatile("mma.sync.aligned.m16n8k16.row.col.f32.bf16.bf16.f32 "
        "{%0,%1,%2,%3}, {%4,%5,%6,%7}, {%8,%9}, {%0,%1,%2,%3};"
        : "+f"(c[0]), "+f"(c[1]), "+f"(c[2]), "+f"(c[3])
        : "r"(a[0]), "r"(a[1]), "r"(a[2]), "r"(a[3]), "r"(b0), "r"(b1));
}
__device__ __forceinline__ u32 swz(u32 b) { return b ^ ((b >> 3) & 0x70); }

__device__ __forceinline__ u64 pk2(float lo, float hi) {
    u64 r; asm("mov.b64 %0, {%1, %2};" : "=l"(r) : "f"(lo), "f"(hi)); return r;
}
__device__ __forceinline__ u64 splat2(float x) {
    u64 r; asm("mov.b64 %0, {%1, %1};" : "=l"(r) : "f"(x)); return r;
}
__device__ __forceinline__ u64 ffma2(u64 a, u64 b, u64 c) {
    u64 d; asm("fma.rn.f32x2 %0, %1, %2, %3;" : "=l"(d) : "l"(a), "l"(b), "l"(c));
    return d;
}
__device__ __forceinline__ void upk2u(u64 v, u32& lo, u32& hi) {
    asm("mov.b64 {%0, %1}, %2;" : "=r"(lo), "=r"(hi) : "l"(v));
}

// packed exp(y0), exp(y1) for y in [-87, 0] (exact pre-subtracted inputs).
__device__ __forceinline__ void exp2pair(float y0, float y1, float& e0, float& e1) {
    const u64 L2E2 = splat2(1.44269504088896f);
    const u64 MAGIC = splat2(12582912.0f);
    u64 y2 = pk2(y0, y1);
    u64 t2 = ffma2(y2, L2E2, MAGIC);
    u64 s2 = ffma2(t2, splat2(-1.f), MAGIC);
    u64 f2 = ffma2(y2, L2E2, s2);
    u64 p2 = ffma2(f2, splat2(1.3333558e-3f), splat2(9.6181291e-3f));
    p2 = ffma2(f2, p2, splat2(5.5504109e-2f));
    p2 = ffma2(f2, p2, splat2(2.4022651e-1f));
    p2 = ffma2(f2, p2, splat2(6.9314718e-1f));
    p2 = ffma2(f2, p2, splat2(1.0f));
    u32 tl, th, pl, ph;
    upk2u(t2, tl, th);
    upk2u(p2, pl, ph);
    e0 = __uint_as_float(pl + (tl << 23));
    e1 = __uint_as_float(ph + (th << 23));
}

__device__ __forceinline__ void hl2(float x, float y, u32& h, u32& l) {
    __nv_bfloat16 hx = __float2bfloat16(x), hy = __float2bfloat16(y);
    __nv_bfloat16 lx = __float2bfloat16(x - __bfloat162float(hx));
    __nv_bfloat16 ly = __float2bfloat16(y - __bfloat162float(hy));
    __nv_bfloat162 hh = __halves2bfloat162(hx, hy), ll = __halves2bfloat162(lx, ly);
    h = *(u32*)&hh; l = *(u32*)&ll;
}
__device__ __forceinline__ void cvt8(float4 a, float4 b2, uint4& h, uint4& l) {
    hl2(a.x, a.y, h.x, l.x); hl2(a.z, a.w, h.y, l.y);
    hl2(b2.x, b2.y, h.z, l.z); hl2(b2.z, b2.w, h.w, l.w);
}

__device__ float g_w[N_W];
__device__ float g_qkv[(size_t)TT * BB * 3 * 512];
__device__ float g_r[(size_t)TT * 512];
__device__ __nv_bfloat16 g_ah[2097152], g_al[2097152];
__device__ __nv_bfloat16 g_wh[1310720], g_wl[1310720];
__device__ __nv_bfloat16 g_qh[6291456], g_ql[6291456];
__device__ __nv_bfloat16 g_rh[1048576], g_rl[1048576];
__device__ float g_corr[16384];   // [n][m]

// ---------------------------------------------------------------------------
__global__ void k_sample_w(const float* __restrict__ mu, const float* __restrict__ rho,
                           const float* __restrict__ eps, float* __restrict__ w,
                           __nv_bfloat16* __restrict__ wh, __nv_bfloat16* __restrict__ wl) {
    int i = blockIdx.x * blockDim.x + threadIdx.x;
    if (i < N_W) {
        float r = rho[i];
        float sp = (r > 20.f) ? r : log1pf(expf(r));
        float v = fmaf(sp, eps[i], mu[i]);
        w[i] = v;
        if (i < 1310720) {
            __nv_bfloat16 h = __float2bfloat16(v);
            wh[i] = h;
            wl[i] = __float2bfloat16(v - __bfloat162float(h));
        }
    }
}

__global__ void k_split(const float* __restrict__ x, __nv_bfloat16* __restrict__ hi,
                        __nv_bfloat16* __restrict__ lo, int n) {
    int i = blockIdx.x * blockDim.x + threadIdx.x;
    if (i < n) {
        float v = x[i];
        __nv_bfloat16 h = __float2bfloat16(v);
        hi[i] = h;
        lo[i] = __float2bfloat16(v - __bfloat162float(h));
    }
}

// corr_g[n][m] = sum_k (rrb[n][k]-rwb[n][k]) * r[m][n*64+k]
__global__ void k_corr(const float* __restrict__ rbuf, const float* __restrict__ w,
                       float* __restrict__ cg) {
    int idx = blockIdx.x * blockDim.x + threadIdx.x;
    if (idx >= 16384) return;
    int n = idx >> 11, m = idx & 2047;
    const float4* rr = (const float4*)(rbuf + (size_t)m * 512 + n * 64);
    const float4* da = (const float4*)(g_w + OFF_RRB + n * 64);
    const float4* db = (const float4*)(g_w + OFF_RWB + n * 64);
    float s = 0.f;
#pragma unroll
    for (int k4 = 0; k4 < 16; k4++) {
        float4 rv = rr[k4], a = da[k4], b = db[k4];
        s = fmaf(a.x - b.x, rv.x, s); s = fmaf(a.y - b.y, rv.y, s);
        s = fmaf(a.z - b.z, rv.z, s); s = fmaf(a.w - b.w, rv.w, s);
    }
    cg[idx] = s;
}

// ---------------------------------------------------------------------------
// HMMA GEMM (proven): C = A @ W^T + bias, bf16 hi/lo 3-pass.
// ---------------------------------------------------------------------------
#define GS_AH 0
#define GS_AL 16384
#define GS_BH 32768
#define GS_BL 49152
#define SMEM_G 65536

__global__ __launch_bounds__(256, 2)
void k_hgemm(const __nv_bfloat16* __restrict__ Ah, const __nv_bfloat16* __restrict__ Al,
             const __nv_bfloat16* __restrict__ Wh, const __nv_bfloat16* __restrict__ Wl,
             const float* __restrict__ bias, float* __restrict__ C, int M, int N) {
    extern __shared__ char smem[];
    const u32 sb = s2u(smem);
    const int tid = threadIdx.x, lane = tid & 31, warp = tid >> 5;
    const int m0 = blockIdx.y * 128, n0 = blockIdx.x * 128;
    const int wm = (warp >> 2) * 64, wn = (warp & 3) * 32;
    const int rA = (lane & 7) + ((lane >> 3) & 1) * 8;
    const int cA = ((lane >> 4) & 1) * 16;
    const int rB = (lane & 7) + ((lane >> 4) & 1) * 8;
    const int cB = ((lane >> 3) & 1) * 16;

    float acc[4][4][4];
#pragma unroll
    for (int u = 0; u < 4; u++)
#pragma unroll
        for (int t = 0; t < 4; t++)
#pragma unroll
            for (int e = 0; e < 4; e++) acc[u][t][e] = 0.f;

    for (int c = 0; c < 8; c++) {
        __syncthreads();
#pragma unroll
        for (int p = 0; p < 4; p++) {
            int idx = p * 256 + tid;
            int row = idx >> 3, c8 = idx & 7;
            u32 off = swz(row * 128 + c8 * 16);
            size_t ga = (size_t)(m0 + row) * 512 + c * 64 + c8 * 8;
            size_t gb = (size_t)(n0 + row) * 512 + c * 64 + c8 * 8;
            *(uint4*)(smem + GS_AH + off) = *(const uint4*)(Ah + ga);
            *(uint4*)(smem + GS_AL + off) = *(const uint4*)(Al + ga);
            *(uint4*)(smem + GS_BH + off) = *(const uint4*)(Wh + gb);
            *(uint4*)(smem + GS_BL + off) = *(const uint4*)(Wl + gb);
        }
        __syncthreads();
#pragma unroll
        for (int s = 0; s < 4; s++) {
            u32 ah[4][4], al[4][4];
#pragma unroll
            for (int u = 0; u < 4; u++) {
                u32 off = swz((wm + u * 16 + rA) * 128 + cA + s * 32);
                ldm4(ah[u], sb + GS_AH + off);
                ldm4(al[u], sb + GS_AL + off);
            }
#pragma unroll
            for (int t = 0; t < 2; t++) {
                u32 bh[4], bl[4];
                u32 off = swz((wn + t * 16 + rB) * 128 + cB + s * 32);
                ldm4(bh, sb + GS_BH + off);
                ldm4(bl, sb + GS_BL + off);
#pragma unroll
                for (int h = 0; h < 2; h++) {
                    int n8 = t * 2 + h;
#pragma unroll
                    for (int u = 0; u < 4; u++) {
                        mma_bf16(acc[u][n8], ah[u], bh[2 * h], bh[2 * h + 1]);
                        mma_bf16(acc[u][n8], ah[u], bl[2 * h], bl[2 * h + 1]);
                        mma_bf16(acc[u][n8], al[u], bh[2 * h], bh[2 * h + 1]);
                    }
                }
            }
        }
    }
#pragma unroll
    for (int u = 0; u < 4; u++)
#pragma unroll
        for (int n8 = 0; n8 < 4; n8++) {
            int col = n0 + wn + n8 * 8 + 2 * (lane & 3);
            int row = m0 + wm + u * 16 + (lane >> 2);
            float2 bv = *(const float2*)(bias + col);
            *(float2*)(C + (size_t)row * N + col) =
                make_float2(acc[u][n8][0] + bv.x, acc[u][n8][1] + bv.y);
            *(float2*)(C + (size_t)(row + 8) * N + col) =
                make_float2(acc[u][n8][2] + bv.x, acc[u][n8][3] + bv.y);
        }
}

// ---------------------------------------------------------------------------
// Tensor-core flash attention, rel-shift fused, pre-split K/V/R, precomputed
// corr, Sb aliased over K+R (97.3 KB -> 2 CTAs/SM). Writes att as bf16 hi/lo.
// ---------------------------------------------------------------------------
#define TF_QWH 0
#define TF_QWL 8192
#define TF_KH  16384
#define TF_KL  24576
#define TF_RH  32768
#define TF_RL  49152
#define TF_VH  65536
#define TF_VL  73728
#define TF_PH  81920
#define TF_PL  90112
#define TF_SC  98304
#define TF_LI  98560
#define TF_CO  98816
#define TF_TOT 99584

__global__ __launch_bounds__(256, 2)
void k_tflash(const float* __restrict__ qkv,
              const __nv_bfloat16* __restrict__ qh, const __nv_bfloat16* __restrict__ ql,
              const __nv_bfloat16* __restrict__ rh, const __nv_bfloat16* __restrict__ rl,
              const float* __restrict__ corrg, const float* __restrict__ w,
              __nv_bfloat16* __restrict__ oh, __nv_bfloat16* __restrict__ ol) {
    extern __shared__ char smem[];
    float* Sb    = (float*)(smem + TF_KH);    // aliased over KH..RL, [64][191]
    float* scale = (float*)(smem + TF_SC);
    float* linv  = (float*)(smem + TF_LI);
    float* corr  = (float*)(smem + TF_CO);
    const u32 sb = s2u(smem);
    const int combo = blockIdx.x, b = combo >> 3, n = combo & 7;
    const int it = 31 - (int)blockIdx.y, i0 = it * 64;
    const int tid = threadIdx.x, lane = tid & 31, warp = tid >> 5;
    const int rA = (lane & 7) + ((lane >> 3) & 1) * 8;
    const int cA = ((lane >> 4) & 1) * 16;
    const int rB = (lane & 7) + ((lane >> 4) & 1) * 8;
    const int cB = ((lane >> 3) & 1) * 16;
    const int mi2 = (warp >> 2) * 32;
    const int nc0 = (warp & 3) * 48;
    const int d0 = (warp & 3) * 16;
    const int si = tid >> 2, jg = tid & 3;

#pragma unroll
    for (int p = 0; p < 2; p++) {
        int c = p * 256 + tid;
        int row = c >> 3, c8 = (c & 7) * 8;
        const float* qg = qkv + ((size_t)(i0 + row) * BB + b) * 1536 + n * 64 + c8;
        const float* bg = w + OFF_RWB + n * 64 + c8;
        float4 a = *(const float4*)qg, a2 = *(const float4*)(qg + 4);
        float4 bw = *(const float4*)bg, bw2 = *(const float4*)(bg + 4);
        a.x += bw.x; a.y += bw.y; a.z += bw.z; a.w += bw.w;
        a2.x += bw2.x; a2.y += bw2.y; a2.z += bw2.z; a2.w += bw2.w;
        uint4 h, l; cvt8(a, a2, h, l);
        u32 off = swz(row * 128 + c8 * 2);
        *(uint4*)(smem + TF_QWH + off) = h;
        *(uint4*)(smem + TF_QWL + off) = l;
    }

    float mrun = -1e30f, lrun = 0.f;
    float o[2][2][4];
#pragma unroll
    for (int u = 0; u < 2; u++)
#pragma unroll
        for (int h = 0; h < 2; h++)
#pragma unroll
            for (int e = 0; e < 4; e++) o[u][h][e] = 0.f;

    for (int jt = 0; jt <= it; jt++) {
        const int j0 = jt * 64;
        __syncthreads();   // prev Sb/P/V reads done
        // stage K, V (pure copies of pre-split bf16)
#pragma unroll
        for (int p = 0; p < 2; p++) {
            int c = p * 256 + tid;
            int row = c >> 3, c8 = (c & 7) * 8;
            size_t base = ((size_t)(j0 + row) * BB + b) * 1536 + n * 64 + c8;
            u32 off = swz(row * 128 + c8 * 2);
            *(uint4*)(smem + TF_KH + off) = *(const uint4*)(qh + base + 512);
            *(uint4*)(smem + TF_KL + off) = *(const uint4*)(ql + base + 512);
            *(uint4*)(smem + TF_VH + off) = *(const uint4*)(qh + base + 1024);
            *(uint4*)(smem + TF_VL + off) = *(const uint4*)(ql + base + 1024);
        }
        // stage R band (pure copies)
        const int m_base = j0 - i0 + 1984;
#pragma unroll
        for (int p = 0; p < 4; p++) {
            int c = p * 256 + tid;
            int dd = c >> 3, c8 = (c & 7) * 8;
            int gm = m_base + dd;
            uint4 h = make_uint4(0, 0, 0, 0), l = h;
            if (dd < 127 && gm < TT) {
                size_t base = (size_t)gm * 512 + n * 64 + c8;
                h = *(const uint4*)(rh + base);
                l = *(const uint4*)(rl + base);
            }
            u32 off = swz(dd * 128 + c8 * 2);
            *(uint4*)(smem + TF_RH + off) = h;
            *(uint4*)(smem + TF_RL + off) = l;
        }
        if (tid < 127) {
            int gm = m_base + tid;
            corr[tid] = (gm < TT) ? corrg[n * 2048 + gm] : 0.f;
        }
        __syncthreads();

        // ---- S GEMM (reads QW, K, R) ----
        float c48[2][6][4];
#pragma unroll
        for (int u = 0; u < 2; u++)
#pragma unroll
            for (int t = 0; t < 6; t++)
#pragma unroll
                for (int e = 0; e < 4; e++) c48[u][t][e] = 0.f;
#pragma unroll
        for (int kk = 0; kk < 4; kk++) {
            u32 ah[2][4], al[2][4];
#pragma unroll
            for (int u = 0; u < 2; u++) {
                u32 off = swz((mi2 + u * 16 + rA) * 128 + cA + kk * 32);
                ldm4(ah[u], sb + TF_QWH + off);
                ldm4(al[u], sb + TF_QWL + off);
            }
#pragma unroll
            for (int nt = 0; nt < 3; nt++) {
                int col0 = nc0 + nt * 16;
                u32 bufh = (col0 < 64) ? TF_KH : TF_RH;
                u32 bufl = (col0 < 64) ? TF_KL : TF_RL;
                int brow = (col0 < 64) ? col0 : col0 - 64;
                u32 bh[4], bl[4];
                u32 off = swz((brow + rB) * 128 + cB + kk * 32);
                ldm4(bh, sb + bufh + off);
                ldm4(bl, sb + bufl + off);
#pragma unroll
                for (int u = 0; u < 2; u++)
#pragma unroll
                    for (int h = 0; h < 2; h++) {
                        float* cc = c48[u][nt * 2 + h];
                        mma_bf16(cc, ah[u], bh[2 * h], bh[2 * h + 1]);
                        mma_bf16(cc, ah[u], bl[2 * h], bl[2 * h + 1]);
                        mma_bf16(cc, al[u], bh[2 * h], bh[2 * h + 1]);
                    }
            }
        }
        __syncthreads();   // K/R reads done before Sb alias writes

        // ---- S store (Sb aliases K/R; stride 191) ----
#pragma unroll
        for (int u = 0; u < 2; u++)
#pragma unroll
            for (int t = 0; t < 6; t++) {
                int row = mi2 + u * 16 + (lane >> 2);
                int col = nc0 + t * 8 + (lane & 3) * 2;
                Sb[row * 191 + col] = c48[u][t][0];
                Sb[(row + 8) * 191 + col] = c48[u][t][2];
                if (col < 190) {
                    Sb[row * 191 + col + 1] = c48[u][t][1];
                    Sb[(row + 8) * 191 + col + 1] = c48[u][t][3];
                }
            }
        __syncthreads();

        // ---- softmax (FMA-pipe exp) ----
        {
            float pv[16];
            float mloc = -1e30f;
            const float* srow = Sb + si * 191;
#pragma unroll
            for (int jj = 0; jj < 16; jj++) {
                int j = jg * 16 + jj;
                float v = -1e30f;
                if (jt < it || j <= si) {
                    int dd = j - si + 63;
                    v = 0.125f * (srow[j] + srow[64 + dd] + corr[dd]);
                }
                pv[jj] = v;
                mloc = fmaxf(mloc, v);
            }
            mloc = fmaxf(mloc, __shfl_xor_sync(0xffffffffu, mloc, 1));
            mloc = fmaxf(mloc, __shfl_xor_sync(0xffffffffu, mloc, 2));
            float mnew = fmaxf(mrun, mloc);
            float sc = __expf(mrun - mnew);
            mrun = mnew;
            float ls = 0.f;
            u32 hb[8], lb[8];
#pragma unroll
            for (int q = 0; q < 8; q++) {
                float y0 = fmaxf(pv[2 * q] - mnew, -80.f);
                float y1 = fmaxf(pv[2 * q + 1] - mnew, -80.f);
                float p0, p1;
                exp2pair(y0, y1, p0, p1);
                ls += p0 + p1;
                hl2(p0, p1, hb[q], lb[q]);
            }
            ls += __shfl_xor_sync(0xffffffffu, ls, 1);
            ls += __shfl_xor_sync(0xffffffffu, ls, 2);
            lrun = lrun * sc + ls;
            if ((tid & 3) == 0) scale[si] = sc;
            u32 off0 = swz(si * 128 + jg * 32), off1 = swz(si * 128 + jg * 32 + 16);
            *(uint4*)(smem + TF_PH + off0) = make_uint4(hb[0], hb[1], hb[2], hb[3]);
            *(uint4*)(smem + TF_PH + off1) = make_uint4(hb[4], hb[5], hb[6], hb[7]);
            *(uint4*)(smem + TF_PL + off0) = make_uint4(lb[0], lb[1], lb[2], lb[3]);
            *(uint4*)(smem + TF_PL + off1) = make_uint4(lb[4], lb[5], lb[6], lb[7]);
        }
        __syncthreads();

        // ---- PV ----
#pragma unroll
        for (int u = 0; u < 2; u++) {
            float sA_ = scale[mi2 + u * 16 + (lane >> 2)];
            float sB_ = scale[mi2 + u * 16 + 8 + (lane >> 2)];
#pragma unroll
            for (int h = 0; h < 2; h++) {
                o[u][h][0] *= sA_; o[u][h][1] *= sA_;
                o[u][h][2] *= sB_; o[u][h][3] *= sB_;
            }
        }
#pragma unroll
        for (int kk = 0; kk < 4; kk++) {
            u32 ph[2][4], pl[2][4];
#pragma unroll
            for (int u = 0; u < 2; u++) {
                u32 off = swz((mi2 + u * 16 + rA) * 128 + cA + kk * 32);
                ldm4(ph[u], sb + TF_PH + off);
                ldm4(pl[u], sb + TF_PL + off);
            }
            u32 vh[4], vl[4];
            u32 vo = swz((kk * 16 + rA) * 128 + d0 * 2 + cA);
            ldm4t(vh, sb + TF_VH + vo);
            ldm4t(vl, sb + TF_VL + vo);
#pragma unroll
            for (int u = 0; u < 2; u++)
#pragma unroll
                for (int h = 0; h < 2; h++) {
                    mma_bf16(o[u][h], ph[u], vh[2 * h], vh[2 * h + 1]);
                    mma_bf16(o[u][h], ph[u], vl[2 * h], vl[2 * h + 1]);
                    mma_bf16(o[u][h], pl[u], vh[2 * h], vh[2 * h + 1]);
                }
        }
    }

    if ((tid & 3) == 0) linv[si] = 1.f / lrun;
    __syncthreads();
#pragma unroll
    for (int u = 0; u < 2; u++) {
        int r0 = mi2 + u * 16 + (lane >> 2);
        float i0v = linv[r0], i1v = linv[r0 + 8];
#pragma unroll
        for (int h = 0; h < 2; h++) {
            int col = d0 + h * 8 + (lane & 3) * 2;
            size_t ix0 = ((size_t)(i0 + r0) * BB + b) * 512 + n * 64 + col;
            size_t ix1 = ((size_t)(i0 + r0 + 8) * BB + b) * 512 + n * 64 + col;
            u32 hh, ll;
            hl2(o[u][h][0] * i0v, o[u][h][1] * i0v, hh, ll);
            *(u32*)(oh + ix0) = hh; *(u32*)(ol + ix0) = ll;
            hl2(o[u][h][2] * i1v, o[u][h][3] * i1v, hh, ll);
            *(u32*)(oh + ix1) = hh; *(u32*)(ol + ix1) = ll;
        }
    }
}

// ---------------------------------------------------------------------------
extern "C" void kernel_launch(void* const* d_in, const int* in_sizes, int n_in,
                              void* d_out, int out_size) {
    const float* input = (const float*)d_in[0];
    const float* pos   = (const float*)d_in[1];
    const float* mu    = (const float*)d_in[3];
    const float* rho   = (const float*)d_in[4];
    const float* eps   = (const float*)d_in[5];
    float* out = (float*)d_out;

    float *w, *qkv, *r, *corrg;
    __nv_bfloat16 *ah, *al, *wh, *wl, *qh, *ql, *rh, *rl;
    cudaGetSymbolAddress((void**)&w,    g_w);
    cudaGetSymbolAddress((void**)&qkv,  g_qkv);
    cudaGetSymbolAddress((void**)&r,    g_r);
    cudaGetSymbolAddress((void**)&ah,   g_ah);
    cudaGetSymbolAddress((void**)&al,   g_al);
    cudaGetSymbolAddress((void**)&wh,   g_wh);
    cudaGetSymbolAddress((void**)&wl,   g_wl);
    cudaGetSymbolAddress((void**)&qh,   g_qh);
    cudaGetSymbolAddress((void**)&ql,   g_ql);
    cudaGetSymbolAddress((void**)&rh,   g_rh);
    cudaGetSymbolAddress((void**)&rl,   g_rl);
    cudaGetSymbolAddress((void**)&corrg, g_corr);

    static bool attr_set = false;
    if (!attr_set) {
        cudaFuncSetAttribute(k_hgemm, cudaFuncAttributeMaxDynamicSharedMemorySize, SMEM_G);
        cudaFuncSetAttribute(k_tflash, cudaFuncAttributeMaxDynamicSharedMemorySize, TF_TOT);
        attr_set = true;
    }

    k_sample_w<<<(N_W + 255) / 256, 256>>>(mu, rho, eps, w, wh, wl);

    // qkv = input @ in_w^T + in_b, then split to bf16 hi/lo
    k_split<<<(2097152 + 255) / 256, 256>>>(input, ah, al, 2097152);
    k_hgemm<<<dim3(12, 32), 256, SMEM_G>>>(ah, al, wh + OFF_INW, wl + OFF_INW,
                                           w + OFF_INB, qkv, 4096, 1536);
    k_split<<<(6291456 + 255) / 256, 256>>>(qkv, qh, ql, 6291456);

    // r = pos @ pos_w^T + pos_b, then split + corr
    k_split<<<(1048576 + 255) / 256, 256>>>(pos, ah, al, 1048576);
    k_hgemm<<<dim3(4, 16), 256, SMEM_G>>>(ah, al, wh + OFF_POSW, wl + OFF_POSW,
                                          w + OFF_POSB, r, 2048, 512);
    k_split<<<(1048576 + 255) / 256, 256>>>(r, rh, rl, 1048576);
    k_corr<<<64, 256>>>(r, w, corrg);

    // flash attention -> writes att hi/lo into ah/al
    k_tflash<<<dim3(BB * NHH, 32), 256, TF_TOT>>>(qkv, qh, ql, rh, rl, corrg, w, ah, al);

    // out = att @ out_w^T + out_b
    k_hgemm<<<dim3(4, 32), 256, SMEM_G>>>(ah, al, wh + OFF_OUTW, wl + OFF_OUTW,
                                          w + OFF_OUTB, out, 4096, 512);
}

// round 16
// speedup vs baseline: 1.2312x; 1.0751x over previous
#include <cuda_runtime.h>
#include <cuda_bf16.h>
#include <cstdint>
#include <math.h>

#define TT  2048
#define BB  2
#define NHH 8

#define OFF_INW   0
#define OFF_OUTW  786432
#define OFF_POSW  1048576
#define OFF_INB   1310720
#define OFF_OUTB  1312256
#define OFF_POSB  1312768
#define OFF_RWB   1313280
#define OFF_RRB   1313792
#define N_W       1314304

typedef unsigned long long u64;
typedef unsigned int u32;

__device__ __forceinline__ u32 s2u(const void* p) {
    u32 a;
    asm("{.reg .u64 t; cvta.to.shared.u64 t, %1; cvt.u32.u64 %0, t;}" : "=r"(a) : "l"(p));
    return a;
}
__device__ __forceinline__ void ldm4(u32* r, u32 addr) {
    asm volatile("ldmatrix.sync.aligned.m8n8.x4.shared.b16 {%0,%1,%2,%3}, [%4];"
        : "=r"(r[0]), "=r"(r[1]), "=r"(r[2]), "=r"(r[3]) : "r"(addr));
}
__device__ __forceinline__ void ldm4t(u32* r, u32 addr) {
    asm volatile("ldmatrix.sync.aligned.m8n8.x4.trans.shared.b16 {%0,%1,%2,%3}, [%4];"
        : "=r"(r[0]), "=r"(r[1]), "=r"(r[2]), "=r"(r[3]) : "r"(addr));
}
__device__ __forceinline__ void mma_bf16(float* c, const u32* a, u32 b0, u32 b1) {
    asm volatile("mma.sync.aligned.m16n8k16.row.col.f32.bf16.bf16.f32 "
        "{%0,%1,%2,%3}, {%4,%5,%6,%7}, {%8,%9}, {%0,%1,%2,%3};"
        : "+f"(c[0]), "+f"(c[1]), "+f"(c[2]), "+f"(c[3])
        : "r"(a[0]), "r"(a[1]), "r"(a[2]), "r"(a[3]), "r"(b0), "r"(b1));
}
__device__ __forceinline__ u32 swz(u32 b) { return b ^ ((b >> 3) & 0x70); }

__device__ __forceinline__ u64 pk2(float lo, float hi) {
    u64 r; asm("mov.b64 %0, {%1, %2};" : "=l"(r) : "f"(lo), "f"(hi)); return r;
}
__device__ __forceinline__ u64 splat2(float x) {
    u64 r; asm("mov.b64 %0, {%1, %1};" : "=l"(r) : "f"(x)); return r;
}
__device__ __forceinline__ u64 ffma2(u64 a, u64 b, u64 c) {
    u64 d; asm("fma.rn.f32x2 %0, %1, %2, %3;" : "=l"(d) : "l"(a), "l"(b), "l"(c));
    return d;
}
__device__ __forceinline__ void upk2u(u64 v, u32& lo, u32& hi) {
    asm("mov.b64 {%0, %1}, %2;" : "=r"(lo), "=r"(hi) : "l"(v));
}

// packed exp(y0), exp(y1) for y in [-87, 0] (exact pre-subtracted inputs).
__device__ __forceinline__ void exp2pair(float y0, float y1, float& e0, float& e1) {
    const u64 L2E2 = splat2(1.44269504088896f);
    const u64 MAGIC = splat2(12582912.0f);
    u64 y2 = pk2(y0, y1);
    u64 t2 = ffma2(y2, L2E2, MAGIC);
    u64 s2 = ffma2(t2, splat2(-1.f), MAGIC);
    u64 f2 = ffma2(y2, L2E2, s2);
    u64 p2 = ffma2(f2, splat2(1.3333558e-3f), splat2(9.6181291e-3f));
    p2 = ffma2(f2, p2, splat2(5.5504109e-2f));
    p2 = ffma2(f2, p2, splat2(2.4022651e-1f));
    p2 = ffma2(f2, p2, splat2(6.9314718e-1f));
    p2 = ffma2(f2, p2, splat2(1.0f));
    u32 tl, th, pl, ph;
    upk2u(t2, tl, th);
    upk2u(p2, pl, ph);
    e0 = __uint_as_float(pl + (tl << 23));
    e1 = __uint_as_float(ph + (th << 23));
}

__device__ __forceinline__ void hl2(float x, float y, u32& h, u32& l) {
    __nv_bfloat16 hx = __float2bfloat16(x), hy = __float2bfloat16(y);
    __nv_bfloat16 lx = __float2bfloat16(x - __bfloat162float(hx));
    __nv_bfloat16 ly = __float2bfloat16(y - __bfloat162float(hy));
    __nv_bfloat162 hh = __halves2bfloat162(hx, hy), ll = __halves2bfloat162(lx, ly);
    h = *(u32*)&hh; l = *(u32*)&ll;
}
__device__ __forceinline__ void cvt8(float4 a, float4 b2, uint4& h, uint4& l) {
    hl2(a.x, a.y, h.x, l.x); hl2(a.z, a.w, h.y, l.y);
    hl2(b2.x, b2.y, h.z, l.z); hl2(b2.z, b2.w, h.w, l.w);
}

__device__ float g_w[N_W];
__device__ float g_qkv[(size_t)TT * BB * 3 * 512];
__device__ float g_r[(size_t)TT * 512];
__device__ __nv_bfloat16 g_ah[2097152], g_al[2097152];
__device__ __nv_bfloat16 g_wh[1310720], g_wl[1310720];
__device__ __nv_bfloat16 g_qh[6291456], g_ql[6291456];
__device__ __nv_bfloat16 g_rh[1048576], g_rl[1048576];
__device__ float g_corr[16384];   // [n][m]

// ---------------------------------------------------------------------------
__global__ void k_sample_w(const float* __restrict__ mu, const float* __restrict__ rho,
                           const float* __restrict__ eps, float* __restrict__ w,
                           __nv_bfloat16* __restrict__ wh, __nv_bfloat16* __restrict__ wl) {
    int i = blockIdx.x * blockDim.x + threadIdx.x;
    if (i < N_W) {
        float r = rho[i];
        float sp = (r > 20.f) ? r : log1pf(expf(r));
        float v = fmaf(sp, eps[i], mu[i]);
        w[i] = v;
        if (i < 1310720) {
            __nv_bfloat16 h = __float2bfloat16(v);
            wh[i] = h;
            wl[i] = __float2bfloat16(v - __bfloat162float(h));
        }
    }
}

__global__ void k_split(const float* __restrict__ x, __nv_bfloat16* __restrict__ hi,
                        __nv_bfloat16* __restrict__ lo, int n) {
    int i = blockIdx.x * blockDim.x + threadIdx.x;
    if (i < n) {
        float v = x[i];
        __nv_bfloat16 h = __float2bfloat16(v);
        hi[i] = h;
        lo[i] = __float2bfloat16(v - __bfloat162float(h));
    }
}

// corr_g[n][m] = sum_k (rrb[n][k]-rwb[n][k]) * r[m][n*64+k]
__global__ void k_corr(const float* __restrict__ rbuf, const float* __restrict__ w,
                       float* __restrict__ cg) {
    int idx = blockIdx.x * blockDim.x + threadIdx.x;
    if (idx >= 16384) return;
    int n = idx >> 11, m = idx & 2047;
    const float4* rr = (const float4*)(rbuf + (size_t)m * 512 + n * 64);
    const float4* da = (const float4*)(w + OFF_RRB + n * 64);
    const float4* db = (const float4*)(w + OFF_RWB + n * 64);
    float s = 0.f;
#pragma unroll
    for (int k4 = 0; k4 < 16; k4++) {
        float4 rv = rr[k4], a = da[k4], b = db[k4];
        s = fmaf(a.x - b.x, rv.x, s); s = fmaf(a.y - b.y, rv.y, s);
        s = fmaf(a.z - b.z, rv.z, s); s = fmaf(a.w - b.w, rv.w, s);
    }
    cg[idx] = s;
}

// ---------------------------------------------------------------------------
// HMMA GEMM: C = A @ W^T + bias, bf16 hi/lo 3-pass. Optional fused hi/lo
// split of the result into Chi/Clo (nullptr to skip).
// ---------------------------------------------------------------------------
#define GS_AH 0
#define GS_AL 16384
#define GS_BH 32768
#define GS_BL 49152
#define SMEM_G 65536

__global__ __launch_bounds__(256, 2)
void k_hgemm(const __nv_bfloat16* __restrict__ Ah, const __nv_bfloat16* __restrict__ Al,
             const __nv_bfloat16* __restrict__ Wh, const __nv_bfloat16* __restrict__ Wl,
             const float* __restrict__ bias, float* __restrict__ C,
             __nv_bfloat16* __restrict__ Chi, __nv_bfloat16* __restrict__ Clo,
             int M, int N) {
    extern __shared__ char smem[];
    const u32 sb = s2u(smem);
    const int tid = threadIdx.x, lane = tid & 31, warp = tid >> 5;
    const int m0 = blockIdx.y * 128, n0 = blockIdx.x * 128;
    const int wm = (warp >> 2) * 64, wn = (warp & 3) * 32;
    const int rA = (lane & 7) + ((lane >> 3) & 1) * 8;
    const int cA = ((lane >> 4) & 1) * 16;
    const int rB = (lane & 7) + ((lane >> 4) & 1) * 8;
    const int cB = ((lane >> 3) & 1) * 16;

    float acc[4][4][4];
#pragma unroll
    for (int u = 0; u < 4; u++)
#pragma unroll
        for (int t = 0; t < 4; t++)
#pragma unroll
            for (int e = 0; e < 4; e++) acc[u][t][e] = 0.f;

    for (int c = 0; c < 8; c++) {
        __syncthreads();
#pragma unroll
        for (int p = 0; p < 4; p++) {
            int idx = p * 256 + tid;
            int row = idx >> 3, c8 = idx & 7;
            u32 off = swz(row * 128 + c8 * 16);
            size_t ga = (size_t)(m0 + row) * 512 + c * 64 + c8 * 8;
            size_t gb = (size_t)(n0 + row) * 512 + c * 64 + c8 * 8;
            *(uint4*)(smem + GS_AH + off) = *(const uint4*)(Ah + ga);
            *(uint4*)(smem + GS_AL + off) = *(const uint4*)(Al + ga);
            *(uint4*)(smem + GS_BH + off) = *(const uint4*)(Wh + gb);
            *(uint4*)(smem + GS_BL + off) = *(const uint4*)(Wl + gb);
        }
        __syncthreads();
#pragma unroll
        for (int s = 0; s < 4; s++) {
            u32 ah[4][4], al[4][4];
#pragma unroll
            for (int u = 0; u < 4; u++) {
                u32 off = swz((wm + u * 16 + rA) * 128 + cA + s * 32);
                ldm4(ah[u], sb + GS_AH + off);
                ldm4(al[u], sb + GS_AL + off);
            }
#pragma unroll
            for (int t = 0; t < 2; t++) {
                u32 bh[4], bl[4];
                u32 off = swz((wn + t * 16 + rB) * 128 + cB + s * 32);
                ldm4(bh, sb + GS_BH + off);
                ldm4(bl, sb + GS_BL + off);
#pragma unroll
                for (int h = 0; h < 2; h++) {
                    int n8 = t * 2 + h;
#pragma unroll
                    for (int u = 0; u < 4; u++) {
                        mma_bf16(acc[u][n8], ah[u], bh[2 * h], bh[2 * h + 1]);
                        mma_bf16(acc[u][n8], ah[u], bl[2 * h], bl[2 * h + 1]);
                        mma_bf16(acc[u][n8], al[u], bh[2 * h], bh[2 * h + 1]);
                    }
                }
            }
        }
    }
#pragma unroll
    for (int u = 0; u < 4; u++)
#pragma unroll
        for (int n8 = 0; n8 < 4; n8++) {
            int col = n0 + wn + n8 * 8 + 2 * (lane & 3);
            int row = m0 + wm + u * 16 + (lane >> 2);
            float2 bv = *(const float2*)(bias + col);
            float v00 = acc[u][n8][0] + bv.x, v01 = acc[u][n8][1] + bv.y;
            float v10 = acc[u][n8][2] + bv.x, v11 = acc[u][n8][3] + bv.y;
            *(float2*)(C + (size_t)row * N + col) = make_float2(v00, v01);
            *(float2*)(C + (size_t)(row + 8) * N + col) = make_float2(v10, v11);
            if (Chi) {
                u32 hh, ll;
                hl2(v00, v01, hh, ll);
                *(u32*)(Chi + (size_t)row * N + col) = hh;
                *(u32*)(Clo + (size_t)row * N + col) = ll;
                hl2(v10, v11, hh, ll);
                *(u32*)(Chi + (size_t)(row + 8) * N + col) = hh;
                *(u32*)(Clo + (size_t)(row + 8) * N + col) = ll;
            }
        }
}

// ---------------------------------------------------------------------------
// Tensor-core flash attention: pre-split K/V/R, corr folded into Sb at store,
// Sb aliased over K+R (97.3 KB -> 2 CTAs/SM). Writes att as bf16 hi/lo.
// ---------------------------------------------------------------------------
#define TF_QWH 0
#define TF_QWL 8192
#define TF_KH  16384
#define TF_KL  24576
#define TF_RH  32768
#define TF_RL  49152
#define TF_VH  65536
#define TF_VL  73728
#define TF_PH  81920
#define TF_PL  90112
#define TF_SC  98304
#define TF_LI  98560
#define TF_CO  98816
#define TF_TOT 99584

__global__ __launch_bounds__(256, 2)
void k_tflash(const float* __restrict__ qkv,
              const __nv_bfloat16* __restrict__ qh, const __nv_bfloat16* __restrict__ ql,
              const __nv_bfloat16* __restrict__ rh, const __nv_bfloat16* __restrict__ rl,
              const float* __restrict__ corrg, const float* __restrict__ w,
              __nv_bfloat16* __restrict__ oh, __nv_bfloat16* __restrict__ ol) {
    extern __shared__ char smem[];
    float* Sb    = (float*)(smem + TF_KH);    // aliased over KH..RL, [64][191]
    float* scale = (float*)(smem + TF_SC);
    float* linv  = (float*)(smem + TF_LI);
    float* corr  = (float*)(smem + TF_CO);
    const u32 sb = s2u(smem);
    const int combo = blockIdx.x, b = combo >> 3, n = combo & 7;
    const int it = 31 - (int)blockIdx.y, i0 = it * 64;
    const int tid = threadIdx.x, lane = tid & 31, warp = tid >> 5;
    const int rA = (lane & 7) + ((lane >> 3) & 1) * 8;
    const int cA = ((lane >> 4) & 1) * 16;
    const int rB = (lane & 7) + ((lane >> 4) & 1) * 8;
    const int cB = ((lane >> 3) & 1) * 16;
    const int mi2 = (warp >> 2) * 32;
    const int nc0 = (warp & 3) * 48;
    const int d0 = (warp & 3) * 16;
    const int si = tid >> 2, jg = tid & 3;

#pragma unroll
    for (int p = 0; p < 2; p++) {
        int c = p * 256 + tid;
        int row = c >> 3, c8 = (c & 7) * 8;
        const float* qg = qkv + ((size_t)(i0 + row) * BB + b) * 1536 + n * 64 + c8;
        const float* bg = w + OFF_RWB + n * 64 + c8;
        float4 a = *(const float4*)qg, a2 = *(const float4*)(qg + 4);
        float4 bw = *(const float4*)bg, bw2 = *(const float4*)(bg + 4);
        a.x += bw.x; a.y += bw.y; a.z += bw.z; a.w += bw.w;
        a2.x += bw2.x; a2.y += bw2.y; a2.z += bw2.z; a2.w += bw2.w;
        uint4 h, l; cvt8(a, a2, h, l);
        u32 off = swz(row * 128 + c8 * 2);
        *(uint4*)(smem + TF_QWH + off) = h;
        *(uint4*)(smem + TF_QWL + off) = l;
    }

    float mrun = -1e30f, lrun = 0.f;
    float o[2][2][4];
#pragma unroll
    for (int u = 0; u < 2; u++)
#pragma unroll
        for (int h = 0; h < 2; h++)
#pragma unroll
            for (int e = 0; e < 4; e++) o[u][h][e] = 0.f;

    for (int jt = 0; jt <= it; jt++) {
        const int j0 = jt * 64;
        __syncthreads();   // prev Sb/P/V reads done
#pragma unroll
        for (int p = 0; p < 2; p++) {
            int c = p * 256 + tid;
            int row = c >> 3, c8 = (c & 7) * 8;
            size_t base = ((size_t)(j0 + row) * BB + b) * 1536 + n * 64 + c8;
            u32 off = swz(row * 128 + c8 * 2);
            *(uint4*)(smem + TF_KH + off) = *(const uint4*)(qh + base + 512);
            *(uint4*)(smem + TF_KL + off) = *(const uint4*)(ql + base + 512);
            *(uint4*)(smem + TF_VH + off) = *(const uint4*)(qh + base + 1024);
            *(uint4*)(smem + TF_VL + off) = *(const uint4*)(ql + base + 1024);
        }
        const int m_base = j0 - i0 + 1984;
#pragma unroll
        for (int p = 0; p < 4; p++) {
            int c = p * 256 + tid;
            int dd = c >> 3, c8 = (c & 7) * 8;
            int gm = m_base + dd;
            uint4 h = make_uint4(0, 0, 0, 0), l = h;
            if (dd < 127 && gm < TT) {
                size_t base = (size_t)gm * 512 + n * 64 + c8;
                h = *(const uint4*)(rh + base);
                l = *(const uint4*)(rl + base);
            }
            u32 off = swz(dd * 128 + c8 * 2);
            *(uint4*)(smem + TF_RH + off) = h;
            *(uint4*)(smem + TF_RL + off) = l;
        }
        if (tid < 127) {
            int gm = m_base + tid;
            corr[tid] = (gm < TT) ? corrg[n * 2048 + gm] : 0.f;
        }
        __syncthreads();

        // ---- S GEMM (reads QW, K, R) ----
        float c48[2][6][4];
#pragma unroll
        for (int u = 0; u < 2; u++)
#pragma unroll
            for (int t = 0; t < 6; t++)
#pragma unroll
                for (int e = 0; e < 4; e++) c48[u][t][e] = 0.f;
#pragma unroll
        for (int kk = 0; kk < 4; kk++) {
            u32 ah[2][4], al[2][4];
#pragma unroll
            for (int u = 0; u < 2; u++) {
                u32 off = swz((mi2 + u * 16 + rA) * 128 + cA + kk * 32);
                ldm4(ah[u], sb + TF_QWH + off);
                ldm4(al[u], sb + TF_QWL + off);
            }
#pragma unroll
            for (int nt = 0; nt < 3; nt++) {
                int col0 = nc0 + nt * 16;
                u32 bufh = (col0 < 64) ? TF_KH : TF_RH;
                u32 bufl = (col0 < 64) ? TF_KL : TF_RL;
                int brow = (col0 < 64) ? col0 : col0 - 64;
                u32 bh[4], bl[4];
                u32 off = swz((brow + rB) * 128 + cB + kk * 32);
                ldm4(bh, sb + bufh + off);
                ldm4(bl, sb + bufl + off);
#pragma unroll
                for (int u = 0; u < 2; u++)
#pragma unroll
                    for (int h = 0; h < 2; h++) {
                        float* cc = c48[u][nt * 2 + h];
                        mma_bf16(cc, ah[u], bh[2 * h], bh[2 * h + 1]);
                        mma_bf16(cc, ah[u], bl[2 * h], bl[2 * h + 1]);
                        mma_bf16(cc, al[u], bh[2 * h], bh[2 * h + 1]);
                    }
            }
        }
        __syncthreads();   // K/R reads done before Sb alias writes

        // ---- S store (Sb aliases K/R; stride 191; corr folded in for S2) ----
#pragma unroll
        for (int u = 0; u < 2; u++)
#pragma unroll
            for (int t = 0; t < 6; t++) {
                int row = mi2 + u * 16 + (lane >> 2);
                int col = nc0 + t * 8 + (lane & 3) * 2;
                float a0 = (col >= 64) ? corr[col - 64] : 0.f;
                Sb[row * 191 + col] = c48[u][t][0] + a0;
                Sb[(row + 8) * 191 + col] = c48[u][t][2] + a0;
                if (col < 190) {
                    float a1 = (col + 1 >= 64) ? corr[col + 1 - 64] : 0.f;
                    Sb[row * 191 + col + 1] = c48[u][t][1] + a1;
                    Sb[(row + 8) * 191 + col + 1] = c48[u][t][3] + a1;
                }
            }
        __syncthreads();

        // ---- softmax (FMA-pipe exp) ----
        {
            float pv[16];
            float mloc = -1e30f;
            const float* srow = Sb + si * 191;
#pragma unroll
            for (int jj = 0; jj < 16; jj++) {
                int j = jg * 16 + jj;
                float v = -1e30f;
                if (jt < it || j <= si) {
                    int dd = j - si + 63;
                    v = 0.125f * (srow[j] + srow[64 + dd]);
                }
                pv[jj] = v;
                mloc = fmaxf(mloc, v);
            }
            mloc = fmaxf(mloc, __shfl_xor_sync(0xffffffffu, mloc, 1));
            mloc = fmaxf(mloc, __shfl_xor_sync(0xffffffffu, mloc, 2));
            float mnew = fmaxf(mrun, mloc);
            float sc = __expf(mrun - mnew);
            mrun = mnew;
            float ls = 0.f;
            u32 hb[8], lb[8];
#pragma unroll
            for (int q = 0; q < 8; q++) {
                float y0 = fmaxf(pv[2 * q] - mnew, -80.f);
                float y1 = fmaxf(pv[2 * q + 1] - mnew, -80.f);
                float p0, p1;
                exp2pair(y0, y1, p0, p1);
                ls += p0 + p1;
                hl2(p0, p1, hb[q], lb[q]);
            }
            ls += __shfl_xor_sync(0xffffffffu, ls, 1);
            ls += __shfl_xor_sync(0xffffffffu, ls, 2);
            lrun = lrun * sc + ls;
            if ((tid & 3) == 0) scale[si] = sc;
            u32 off0 = swz(si * 128 + jg * 32), off1 = swz(si * 128 + jg * 32 + 16);
            *(uint4*)(smem + TF_PH + off0) = make_uint4(hb[0], hb[1], hb[2], hb[3]);
            *(uint4*)(smem + TF_PH + off1) = make_uint4(hb[4], hb[5], hb[6], hb[7]);
            *(uint4*)(smem + TF_PL + off0) = make_uint4(lb[0], lb[1], lb[2], lb[3]);
            *(uint4*)(smem + TF_PL + off1) = make_uint4(lb[4], lb[5], lb[6], lb[7]);
        }
        __syncthreads();

        // ---- PV ----
#pragma unroll
        for (int u = 0; u < 2; u++) {
            float sA_ = scale[mi2 + u * 16 + (lane >> 2)];
            float sB_ = scale[mi2 + u * 16 + 8 + (lane >> 2)];
#pragma unroll
            for (int h = 0; h < 2; h++) {
                o[u][h][0] *= sA_; o[u][h][1] *= sA_;
                o[u][h][2] *= sB_; o[u][h][3] *= sB_;
            }
        }
#pragma unroll
        for (int kk = 0; kk < 4; kk++) {
            u32 ph[2][4], pl[2][4];
#pragma unroll
            for (int u = 0; u < 2; u++) {
                u32 off = swz((mi2 + u * 16 + rA) * 128 + cA + kk * 32);
                ldm4(ph[u], sb + TF_PH + off);
                ldm4(pl[u], sb + TF_PL + off);
            }
            u32 vh[4], vl[4];
            u32 vo = swz((kk * 16 + rA) * 128 + d0 * 2 + cA);
            ldm4t(vh, sb + TF_VH + vo);
            ldm4t(vl, sb + TF_VL + vo);
#pragma unroll
            for (int u = 0; u < 2; u++)
#pragma unroll
                for (int h = 0; h < 2; h++) {
                    mma_bf16(o[u][h], ph[u], vh[2 * h], vh[2 * h + 1]);
                    mma_bf16(o[u][h], ph[u], vl[2 * h], vl[2 * h + 1]);
                    mma_bf16(o[u][h], pl[u], vh[2 * h], vh[2 * h + 1]);
                }
        }
    }

    if ((tid & 3) == 0) linv[si] = 1.f / lrun;
    __syncthreads();
#pragma unroll
    for (int u = 0; u < 2; u++) {
        int r0 = mi2 + u * 16 + (lane >> 2);
        float i0v = linv[r0], i1v = linv[r0 + 8];
#pragma unroll
        for (int h = 0; h < 2; h++) {
            int col = d0 + h * 8 + (lane & 3) * 2;
            size_t ix0 = ((size_t)(i0 + r0) * BB + b) * 512 + n * 64 + col;
            size_t ix1 = ((size_t)(i0 + r0 + 8) * BB + b) * 512 + n * 64 + col;
            u32 hh, ll;
            hl2(o[u][h][0] * i0v, o[u][h][1] * i0v, hh, ll);
            *(u32*)(oh + ix0) = hh; *(u32*)(ol + ix0) = ll;
            hl2(o[u][h][2] * i1v, o[u][h][3] * i1v, hh, ll);
            *(u32*)(oh + ix1) = hh; *(u32*)(ol + ix1) = ll;
        }
    }
}

// ---------------------------------------------------------------------------
extern "C" void kernel_launch(void* const* d_in, const int* in_sizes, int n_in,
                              void* d_out, int out_size) {
    const float* input = (const float*)d_in[0];
    const float* pos   = (const float*)d_in[1];
    const float* mu    = (const float*)d_in[3];
    const float* rho   = (const float*)d_in[4];
    const float* eps   = (const float*)d_in[5];
    float* out = (float*)d_out;

    float *w, *qkv, *r, *corrg;
    __nv_bfloat16 *ah, *al, *wh, *wl, *qh, *ql, *rh, *rl;
    cudaGetSymbolAddress((void**)&w,    g_w);
    cudaGetSymbolAddress((void**)&qkv,  g_qkv);
    cudaGetSymbolAddress((void**)&r,    g_r);
    cudaGetSymbolAddress((void**)&ah,   g_ah);
    cudaGetSymbolAddress((void**)&al,   g_al);
    cudaGetSymbolAddress((void**)&wh,   g_wh);
    cudaGetSymbolAddress((void**)&wl,   g_wl);
    cudaGetSymbolAddress((void**)&qh,   g_qh);
    cudaGetSymbolAddress((void**)&ql,   g_ql);
    cudaGetSymbolAddress((void**)&rh,   g_rh);
    cudaGetSymbolAddress((void**)&rl,   g_rl);
    cudaGetSymbolAddress((void**)&corrg, g_corr);

    static bool attr_set = false;
    if (!attr_set) {
        cudaFuncSetAttribute(k_hgemm, cudaFuncAttributeMaxDynamicSharedMemorySize, SMEM_G);
        cudaFuncSetAttribute(k_tflash, cudaFuncAttributeMaxDynamicSharedMemorySize, TF_TOT);
        attr_set = true;
    }

    k_sample_w<<<(N_W + 255) / 256, 256>>>(mu, rho, eps, w, wh, wl);

    // qkv = input @ in_w^T + in_b (fused hi/lo split of result)
    k_split<<<(2097152 + 255) / 256, 256>>>(input, ah, al, 2097152);
    k_hgemm<<<dim3(12, 32), 256, SMEM_G>>>(ah, al, wh + OFF_INW, wl + OFF_INW,
                                           w + OFF_INB, qkv, qh, ql, 4096, 1536);

    // r = pos @ pos_w^T + pos_b (fused split) + corr
    k_split<<<(1048576 + 255) / 256, 256>>>(pos, ah, al, 1048576);
    k_hgemm<<<dim3(4, 16), 256, SMEM_G>>>(ah, al, wh + OFF_POSW, wl + OFF_POSW,
                                          w + OFF_POSB, r, rh, rl, 2048, 512);
    k_corr<<<64, 256>>>(r, w, corrg);

    // flash attention -> writes att hi/lo into ah/al
    k_tflash<<<dim3(BB * NHH, 32), 256, TF_TOT>>>(qkv, qh, ql, rh, rl, corrg, w, ah, al);

    // out = att @ out_w^T + out_b
    k_hgemm<<<dim3(4, 32), 256, SMEM_G>>>(ah, al, wh + OFF_OUTW, wl + OFF_OUTW,
                                          w + OFF_OUTB, out, (__nv_bfloat16*)nullptr,
                                          (__nv_bfloat16*)nullptr, 4096, 512);
}

// round 17
// speedup vs baseline: 1.3825x; 1.1229x over previous
#include <cuda_runtime.h>
#include <cuda_bf16.h>
#include <cstdint>
#include <math.h>

#define TT  2048
#define BB  2
#define NHH 8

#define OFF_INW   0
#define OFF_OUTW  786432
#define OFF_POSW  1048576
#define OFF_INB   1310720
#define OFF_OUTB  1312256
#define OFF_POSB  1312768
#define OFF_RWB   1313280
#define OFF_RRB   1313792
#define N_W       1314304

typedef unsigned long long u64;
typedef unsigned int u32;

__device__ __forceinline__ u32 s2u(const void* p) {
    u32 a;
    asm("{.reg .u64 t; cvta.to.shared.u64 t, %1; cvt.u32.u64 %0, t;}" : "=r"(a) : "l"(p));
    return a;
}
__device__ __forceinline__ void ldm4(u32* r, u32 addr) {
    asm volatile("ldmatrix.sync.aligned.m8n8.x4.shared.b16 {%0,%1,%2,%3}, [%4];"
        : "=r"(r[0]), "=r"(r[1]), "=r"(r[2]), "=r"(r[3]) : "r"(addr));
}
__device__ __forceinline__ void ldm4t(u32* r, u32 addr) {
    asm volatile("ldmatrix.sync.aligned.m8n8.x4.trans.shared.b16 {%0,%1,%2,%3}, [%4];"
        : "=r"(r[0]), "=r"(r[1]), "=r"(r[2]), "=r"(r[3]) : "r"(addr));
}
__device__ __forceinline__ void mma_bf16(float* c, const u32* a, u32 b0, u32 b1) {
    asm volatile("mma.sync.aligned.m16n8k16.row.col.f32.bf16.bf16.f32 "
        "{%0,%1,%2,%3}, {%4,%5,%6,%7}, {%8,%9}, {%0,%1,%2,%3};"
        : "+f"(c[0]), "+f"(c[1]), "+f"(c[2]), "+f"(c[3])
        : "r"(a[0]), "r"(a[1]), "r"(a[2]), "r"(a[3]), "r"(b0), "r"(b1));
}
__device__ __forceinline__ u32 swz(u32 b) { return b ^ ((b >> 3) & 0x70); }

__device__ __forceinline__ void cpa16(u32 saddr, const void* g) {
    asm volatile("cp.async.cg.shared.global [%0], [%1], 16;" :: "r"(saddr), "l"(g));
}
#define CP_COMMIT() asm volatile("cp.async.commit_group;" ::: "memory")
#define CP_WAIT0()  asm volatile("cp.async.wait_group 0;" ::: "memory")
#define CP_WAIT1()  asm volatile("cp.async.wait_group 1;" ::: "memory")

__device__ __forceinline__ u64 pk2(float lo, float hi) {
    u64 r; asm("mov.b64 %0, {%1, %2};" : "=l"(r) : "f"(lo), "f"(hi)); return r;
}
__device__ __forceinline__ u64 splat2(float x) {
    u64 r; asm("mov.b64 %0, {%1, %1};" : "=l"(r) : "f"(x)); return r;
}
__device__ __forceinline__ u64 ffma2(u64 a, u64 b, u64 c) {
    u64 d; asm("fma.rn.f32x2 %0, %1, %2, %3;" : "=l"(d) : "l"(a), "l"(b), "l"(c));
    return d;
}
__device__ __forceinline__ void upk2u(u64 v, u32& lo, u32& hi) {
    asm("mov.b64 {%0, %1}, %2;" : "=r"(lo), "=r"(hi) : "l"(v));
}

// packed exp(y0), exp(y1) for y in [-87, 0] (exact pre-subtracted inputs).
__device__ __forceinline__ void exp2pair(float y0, float y1, float& e0, float& e1) {
    const u64 L2E2 = splat2(1.44269504088896f);
    const u64 MAGIC = splat2(12582912.0f);
    u64 y2 = pk2(y0, y1);
    u64 t2 = ffma2(y2, L2E2, MAGIC);
    u64 s2 = ffma2(t2, splat2(-1.f), MAGIC);
    u64 f2 = ffma2(y2, L2E2, s2);
    u64 p2 = ffma2(f2, splat2(1.3333558e-3f), splat2(9.6181291e-3f));
    p2 = ffma2(f2, p2, splat2(5.5504109e-2f));
    p2 = ffma2(f2, p2, splat2(2.4022651e-1f));
    p2 = ffma2(f2, p2, splat2(6.9314718e-1f));
    p2 = ffma2(f2, p2, splat2(1.0f));
    u32 tl, th, pl, ph;
    upk2u(t2, tl, th);
    upk2u(p2, pl, ph);
    e0 = __uint_as_float(pl + (tl << 23));
    e1 = __uint_as_float(ph + (th << 23));
}

__device__ __forceinline__ void hl2(float x, float y, u32& h, u32& l) {
    __nv_bfloat16 hx = __float2bfloat16(x), hy = __float2bfloat16(y);
    __nv_bfloat16 lx = __float2bfloat16(x - __bfloat162float(hx));
    __nv_bfloat16 ly = __float2bfloat16(y - __bfloat162float(hy));
    __nv_bfloat162 hh = __halves2bfloat162(hx, hy), ll = __halves2bfloat162(lx, ly);
    h = *(u32*)&hh; l = *(u32*)&ll;
}
__device__ __forceinline__ void cvt8(float4 a, float4 b2, uint4& h, uint4& l) {
    hl2(a.x, a.y, h.x, l.x); hl2(a.z, a.w, h.y, l.y);
    hl2(b2.x, b2.y, h.z, l.z); hl2(b2.z, b2.w, h.w, l.w);
}

__device__ float g_w[N_W];
__device__ float g_qkv[(size_t)TT * BB * 3 * 512];
__device__ float g_r[(size_t)TT * 512];
__device__ __nv_bfloat16 g_ah[2097152], g_al[2097152];
__device__ __nv_bfloat16 g_wh[1310720], g_wl[1310720];
__device__ __nv_bfloat16 g_qh[6291456], g_ql[6291456];
__device__ __nv_bfloat16 g_rh[1048576], g_rl[1048576];
__device__ float g_corr[16384];   // [n][m]

// ---------------------------------------------------------------------------
__global__ void k_sample_w(const float* __restrict__ mu, const float* __restrict__ rho,
                           const float* __restrict__ eps, float* __restrict__ w,
                           __nv_bfloat16* __restrict__ wh, __nv_bfloat16* __restrict__ wl) {
    int i = blockIdx.x * blockDim.x + threadIdx.x;
    if (i < N_W) {
        float r = rho[i];
        float sp = (r > 20.f) ? r : log1pf(expf(r));
        float v = fmaf(sp, eps[i], mu[i]);
        w[i] = v;
        if (i < 1310720) {
            __nv_bfloat16 h = __float2bfloat16(v);
            wh[i] = h;
            wl[i] = __float2bfloat16(v - __bfloat162float(h));
        }
    }
}

__global__ void k_split(const float* __restrict__ x, __nv_bfloat16* __restrict__ hi,
                        __nv_bfloat16* __restrict__ lo, int n) {
    int i = blockIdx.x * blockDim.x + threadIdx.x;
    if (i < n) {
        float v = x[i];
        __nv_bfloat16 h = __float2bfloat16(v);
        hi[i] = h;
        lo[i] = __float2bfloat16(v - __bfloat162float(h));
    }
}

// corr_g[n][m] = sum_k (rrb[n][k]-rwb[n][k]) * r[m][n*64+k]
__global__ void k_corr(const float* __restrict__ rbuf, const float* __restrict__ w,
                       float* __restrict__ cg) {
    int idx = blockIdx.x * blockDim.x + threadIdx.x;
    if (idx >= 16384) return;
    int n = idx >> 11, m = idx & 2047;
    const float4* rr = (const float4*)(rbuf + (size_t)m * 512 + n * 64);
    const float4* da = (const float4*)(w + OFF_RRB + n * 64);
    const float4* db = (const float4*)(w + OFF_RWB + n * 64);
    float s = 0.f;
#pragma unroll
    for (int k4 = 0; k4 < 16; k4++) {
        float4 rv = rr[k4], a = da[k4], b = db[k4];
        s = fmaf(a.x - b.x, rv.x, s); s = fmaf(a.y - b.y, rv.y, s);
        s = fmaf(a.z - b.z, rv.z, s); s = fmaf(a.w - b.w, rv.w, s);
    }
    cg[idx] = s;
}

// ---------------------------------------------------------------------------
// HMMA GEMM: C = A @ W^T + bias, bf16 hi/lo 3-pass, cp.async double-buffered.
// Tile 128(M) x 64(N), K chunks of 64. 8 warps = 4M x 2N. Optional fused
// hi/lo split of the result into Chi/Clo (nullptr to skip).
// Buffer layout (48 KB each): AH 0, AL 16384, BH 32768, BL 40960.
// ---------------------------------------------------------------------------
#define GB_SZ 49152
#define SMEM_G 98304

__global__ __launch_bounds__(256, 2)
void k_hgemm(const __nv_bfloat16* __restrict__ Ah, const __nv_bfloat16* __restrict__ Al,
             const __nv_bfloat16* __restrict__ Wh, const __nv_bfloat16* __restrict__ Wl,
             const float* __restrict__ bias, float* __restrict__ C,
             __nv_bfloat16* __restrict__ Chi, __nv_bfloat16* __restrict__ Clo,
             int M, int N) {
    extern __shared__ char smem[];
    const u32 sb = s2u(smem);
    const int tid = threadIdx.x, lane = tid & 31, warp = tid >> 5;
    const int m0 = blockIdx.y * 128, n0 = blockIdx.x * 64;
    const int wm = (warp >> 1) * 32, wn = (warp & 1) * 32;
    const int rA = (lane & 7) + ((lane >> 3) & 1) * 8;
    const int cA = ((lane >> 4) & 1) * 16;
    const int rB = (lane & 7) + ((lane >> 4) & 1) * 8;
    const int cB = ((lane >> 3) & 1) * 16;

    // stage chunk c into buffer at byte-offset bb
    auto stage = [&](int c, u32 bb) {
#pragma unroll
        for (int p = 0; p < 4; p++) {
            int idx = p * 256 + tid;
            int row = idx >> 3, c8 = idx & 7;
            u32 off = swz(row * 128 + c8 * 16);
            size_t ga = (size_t)(m0 + row) * 512 + c * 64 + c8 * 8;
            cpa16(sb + bb + off, Ah + ga);
            cpa16(sb + bb + 16384 + off, Al + ga);
        }
#pragma unroll
        for (int p = 0; p < 2; p++) {
            int idx = p * 256 + tid;
            int row = idx >> 3, c8 = idx & 7;
            u32 off = swz(row * 128 + c8 * 16);
            size_t gb = (size_t)(n0 + row) * 512 + c * 64 + c8 * 8;
            cpa16(sb + bb + 32768 + off, Wh + gb);
            cpa16(sb + bb + 40960 + off, Wl + gb);
        }
    };

    float acc[2][4][4];
#pragma unroll
    for (int u = 0; u < 2; u++)
#pragma unroll
        for (int t = 0; t < 4; t++)
#pragma unroll
            for (int e = 0; e < 4; e++) acc[u][t][e] = 0.f;

    stage(0, 0);
    CP_COMMIT();

    for (int c = 0; c < 8; c++) {
        u32 bb = (c & 1) ? GB_SZ : 0;
        if (c + 1 < 8) {
            stage(c + 1, (c & 1) ? 0 : GB_SZ);
            CP_COMMIT();
            CP_WAIT1();
        } else {
            CP_WAIT0();
        }
        __syncthreads();
#pragma unroll
        for (int s = 0; s < 4; s++) {
            u32 ah[2][4], al[2][4];
#pragma unroll
            for (int u = 0; u < 2; u++) {
                u32 off = swz((wm + u * 16 + rA) * 128 + cA + s * 32);
                ldm4(ah[u], sb + bb + off);
                ldm4(al[u], sb + bb + 16384 + off);
            }
#pragma unroll
            for (int t = 0; t < 2; t++) {
                u32 bh[4], bl[4];
                u32 off = swz((wn + t * 16 + rB) * 128 + cB + s * 32);
                ldm4(bh, sb + bb + 32768 + off);
                ldm4(bl, sb + bb + 40960 + off);
#pragma unroll
                for (int h = 0; h < 2; h++) {
                    int n8 = t * 2 + h;
#pragma unroll
                    for (int u = 0; u < 2; u++) {
                        mma_bf16(acc[u][n8], ah[u], bh[2 * h], bh[2 * h + 1]);
                        mma_bf16(acc[u][n8], ah[u], bl[2 * h], bl[2 * h + 1]);
                        mma_bf16(acc[u][n8], al[u], bh[2 * h], bh[2 * h + 1]);
                    }
                }
            }
        }
        __syncthreads();
    }

#pragma unroll
    for (int u = 0; u < 2; u++)
#pragma unroll
        for (int n8 = 0; n8 < 4; n8++) {
            int col = n0 + wn + n8 * 8 + 2 * (lane & 3);
            int row = m0 + wm + u * 16 + (lane >> 2);
            float2 bv = *(const float2*)(bias + col);
            float v00 = acc[u][n8][0] + bv.x, v01 = acc[u][n8][1] + bv.y;
            float v10 = acc[u][n8][2] + bv.x, v11 = acc[u][n8][3] + bv.y;
            *(float2*)(C + (size_t)row * N + col) = make_float2(v00, v01);
            *(float2*)(C + (size_t)(row + 8) * N + col) = make_float2(v10, v11);
            if (Chi) {
                u32 hh, ll;
                hl2(v00, v01, hh, ll);
                *(u32*)(Chi + (size_t)row * N + col) = hh;
                *(u32*)(Clo + (size_t)row * N + col) = ll;
                hl2(v10, v11, hh, ll);
                *(u32*)(Chi + (size_t)(row + 8) * N + col) = hh;
                *(u32*)(Clo + (size_t)(row + 8) * N + col) = ll;
            }
        }
}

// ---------------------------------------------------------------------------
// Tensor-core flash attention (round-16 proven): pre-split K/V/R, corr folded
// into Sb at store, Sb aliased over K+R (97.3 KB -> 2 CTAs/SM), bf16 hi/lo out.
// ---------------------------------------------------------------------------
#define TF_QWH 0
#define TF_QWL 8192
#define TF_KH  16384
#define TF_KL  24576
#define TF_RH  32768
#define TF_RL  49152
#define TF_VH  65536
#define TF_VL  73728
#define TF_PH  81920
#define TF_PL  90112
#define TF_SC  98304
#define TF_LI  98560
#define TF_CO  98816
#define TF_TOT 99584

__global__ __launch_bounds__(256, 2)
void k_tflash(const float* __restrict__ qkv,
              const __nv_bfloat16* __restrict__ qh, const __nv_bfloat16* __restrict__ ql,
              const __nv_bfloat16* __restrict__ rh, const __nv_bfloat16* __restrict__ rl,
              const float* __restrict__ corrg, const float* __restrict__ w,
              __nv_bfloat16* __restrict__ oh, __nv_bfloat16* __restrict__ ol) {
    extern __shared__ char smem[];
    float* Sb    = (float*)(smem + TF_KH);    // aliased over KH..RL, [64][191]
    float* scale = (float*)(smem + TF_SC);
    float* linv  = (float*)(smem + TF_LI);
    float* corr  = (float*)(smem + TF_CO);
    const u32 sb = s2u(smem);
    const int combo = blockIdx.x, b = combo >> 3, n = combo & 7;
    const int it = 31 - (int)blockIdx.y, i0 = it * 64;
    const int tid = threadIdx.x, lane = tid & 31, warp = tid >> 5;
    const int rA = (lane & 7) + ((lane >> 3) & 1) * 8;
    const int cA = ((lane >> 4) & 1) * 16;
    const int rB = (lane & 7) + ((lane >> 4) & 1) * 8;
    const int cB = ((lane >> 3) & 1) * 16;
    const int mi2 = (warp >> 2) * 32;
    const int nc0 = (warp & 3) * 48;
    const int d0 = (warp & 3) * 16;
    const int si = tid >> 2, jg = tid & 3;

#pragma unroll
    for (int p = 0; p < 2; p++) {
        int c = p * 256 + tid;
        int row = c >> 3, c8 = (c & 7) * 8;
        const float* qg = qkv + ((size_t)(i0 + row) * BB + b) * 1536 + n * 64 + c8;
        const float* bg = w + OFF_RWB + n * 64 + c8;
        float4 a = *(const float4*)qg, a2 = *(const float4*)(qg + 4);
        float4 bw = *(const float4*)bg, bw2 = *(const float4*)(bg + 4);
        a.x += bw.x; a.y += bw.y; a.z += bw.z; a.w += bw.w;
        a2.x += bw2.x; a2.y += bw2.y; a2.z += bw2.z; a2.w += bw2.w;
        uint4 h, l; cvt8(a, a2, h, l);
        u32 off = swz(row * 128 + c8 * 2);
        *(uint4*)(smem + TF_QWH + off) = h;
        *(uint4*)(smem + TF_QWL + off) = l;
    }

    float mrun = -1e30f, lrun = 0.f;
    float o[2][2][4];
#pragma unroll
    for (int u = 0; u < 2; u++)
#pragma unroll
        for (int h = 0; h < 2; h++)
#pragma unroll
            for (int e = 0; e < 4; e++) o[u][h][e] = 0.f;

    for (int jt = 0; jt <= it; jt++) {
        const int j0 = jt * 64;
        __syncthreads();   // prev Sb/P/V reads done
#pragma unroll
        for (int p = 0; p < 2; p++) {
            int c = p * 256 + tid;
            int row = c >> 3, c8 = (c & 7) * 8;
            size_t base = ((size_t)(j0 + row) * BB + b) * 1536 + n * 64 + c8;
            u32 off = swz(row * 128 + c8 * 2);
            *(uint4*)(smem + TF_KH + off) = *(const uint4*)(qh + base + 512);
            *(uint4*)(smem + TF_KL + off) = *(const uint4*)(ql + base + 512);
            *(uint4*)(smem + TF_VH + off) = *(const uint4*)(qh + base + 1024);
            *(uint4*)(smem + TF_VL + off) = *(const uint4*)(ql + base + 1024);
        }
        const int m_base = j0 - i0 + 1984;
#pragma unroll
        for (int p = 0; p < 4; p++) {
            int c = p * 256 + tid;
            int dd = c >> 3, c8 = (c & 7) * 8;
            int gm = m_base + dd;
            uint4 h = make_uint4(0, 0, 0, 0), l = h;
            if (dd < 127 && gm < TT) {
                size_t base = (size_t)gm * 512 + n * 64 + c8;
                h = *(const uint4*)(rh + base);
                l = *(const uint4*)(rl + base);
            }
            u32 off = swz(dd * 128 + c8 * 2);
            *(uint4*)(smem + TF_RH + off) = h;
            *(uint4*)(smem + TF_RL + off) = l;
        }
        if (tid < 127) {
            int gm = m_base + tid;
            corr[tid] = (gm < TT) ? corrg[n * 2048 + gm] : 0.f;
        }
        __syncthreads();

        // ---- S GEMM (reads QW, K, R) ----
        float c48[2][6][4];
#pragma unroll
        for (int u = 0; u < 2; u++)
#pragma unroll
            for (int t = 0; t < 6; t++)
#pragma unroll
                for (int e = 0; e < 4; e++) c48[u][t][e] = 0.f;
#pragma unroll
        for (int kk = 0; kk < 4; kk++) {
            u32 ah[2][4], al[2][4];
#pragma unroll
            for (int u = 0; u < 2; u++) {
                u32 off = swz((mi2 + u * 16 + rA) * 128 + cA + kk * 32);
                ldm4(ah[u], sb + TF_QWH + off);
                ldm4(al[u], sb + TF_QWL + off);
            }
#pragma unroll
            for (int nt = 0; nt < 3; nt++) {
                int col0 = nc0 + nt * 16;
                u32 bufh = (col0 < 64) ? TF_KH : TF_RH;
                u32 bufl = (col0 < 64) ? TF_KL : TF_RL;
                int brow = (col0 < 64) ? col0 : col0 - 64;
                u32 bh[4], bl[4];
                u32 off = swz((brow + rB) * 128 + cB + kk * 32);
                ldm4(bh, sb + bufh + off);
                ldm4(bl, sb + bufl + off);
#pragma unroll
                for (int u = 0; u < 2; u++)
#pragma unroll
                    for (int h = 0; h < 2; h++) {
                        float* cc = c48[u][nt * 2 + h];
                        mma_bf16(cc, ah[u], bh[2 * h], bh[2 * h + 1]);
                        mma_bf16(cc, ah[u], bl[2 * h], bl[2 * h + 1]);
                        mma_bf16(cc, al[u], bh[2 * h], bh[2 * h + 1]);
                    }
            }
        }
        __syncthreads();   // K/R reads done before Sb alias writes

        // ---- S store (Sb aliases K/R; stride 191; corr folded in for S2) ----
#pragma unroll
        for (int u = 0; u < 2; u++)
#pragma unroll
            for (int t = 0; t < 6; t++) {
                int row = mi2 + u * 16 + (lane >> 2);
                int col = nc0 + t * 8 + (lane & 3) * 2;
                float a0 = (col >= 64) ? corr[col - 64] : 0.f;
                Sb[row * 191 + col] = c48[u][t][0] + a0;
                Sb[(row + 8) * 191 + col] = c48[u][t][2] + a0;
                if (col < 190) {
                    float a1 = (col + 1 >= 64) ? corr[col + 1 - 64] : 0.f;
                    Sb[row * 191 + col + 1] = c48[u][t][1] + a1;
                    Sb[(row + 8) * 191 + col + 1] = c48[u][t][3] + a1;
                }
            }
        __syncthreads();

        // ---- softmax (FMA-pipe exp) ----
        {
            float pv[16];
            float mloc = -1e30f;
            const float* srow = Sb + si * 191;
#pragma unroll
            for (int jj = 0; jj < 16; jj++) {
                int j = jg * 16 + jj;
                float v = -1e30f;
                if (jt < it || j <= si) {
                    int dd = j - si + 63;
                    v = 0.125f * (srow[j] + srow[64 + dd]);
                }
                pv[jj] = v;
                mloc = fmaxf(mloc, v);
            }
            mloc = fmaxf(mloc, __shfl_xor_sync(0xffffffffu, mloc, 1));
            mloc = fmaxf(mloc, __shfl_xor_sync(0xffffffffu, mloc, 2));
            float mnew = fmaxf(mrun, mloc);
            float sc = __expf(mrun - mnew);
            mrun = mnew;
            float ls = 0.f;
            u32 hb[8], lb[8];
#pragma unroll
            for (int q = 0; q < 8; q++) {
                float y0 = fmaxf(pv[2 * q] - mnew, -80.f);
                float y1 = fmaxf(pv[2 * q + 1] - mnew, -80.f);
                float p0, p1;
                exp2pair(y0, y1, p0, p1);
                ls += p0 + p1;
                hl2(p0, p1, hb[q], lb[q]);
            }
            ls += __shfl_xor_sync(0xffffffffu, ls, 1);
            ls += __shfl_xor_sync(0xffffffffu, ls, 2);
            lrun = lrun * sc + ls;
            if ((tid & 3) == 0) scale[si] = sc;
            u32 off0 = swz(si * 128 + jg * 32), off1 = swz(si * 128 + jg * 32 + 16);
            *(uint4*)(smem + TF_PH + off0) = make_uint4(hb[0], hb[1], hb[2], hb[3]);
            *(uint4*)(smem + TF_PH + off1) = make_uint4(hb[4], hb[5], hb[6], hb[7]);
            *(uint4*)(smem + TF_PL + off0) = make_uint4(lb[0], lb[1], lb[2], lb[3]);
            *(uint4*)(smem + TF_PL + off1) = make_uint4(lb[4], lb[5], lb[6], lb[7]);
        }
        __syncthreads();

        // ---- PV ----
#pragma unroll
        for (int u = 0; u < 2; u++) {
            float sA_ = scale[mi2 + u * 16 + (lane >> 2)];
            float sB_ = scale[mi2 + u * 16 + 8 + (lane >> 2)];
#pragma unroll
            for (int h = 0; h < 2; h++) {
                o[u][h][0] *= sA_; o[u][h][1] *= sA_;
                o[u][h][2] *= sB_; o[u][h][3] *= sB_;
            }
        }
#pragma unroll
        for (int kk = 0; kk < 4; kk++) {
            u32 ph[2][4], pl[2][4];
#pragma unroll
            for (int u = 0; u < 2; u++) {
                u32 off = swz((mi2 + u * 16 + rA) * 128 + cA + kk * 32);
                ldm4(ph[u], sb + TF_PH + off);
                ldm4(pl[u], sb + TF_PL + off);
            }
            u32 vh[4], vl[4];
            u32 vo = swz((kk * 16 + rA) * 128 + d0 * 2 + cA);
            ldm4t(vh, sb + TF_VH + vo);
            ldm4t(vl, sb + TF_VL + vo);
#pragma unroll
            for (int u = 0; u < 2; u++)
#pragma unroll
                for (int h = 0; h < 2; h++) {
                    mma_bf16(o[u][h], ph[u], vh[2 * h], vh[2 * h + 1]);
                    mma_bf16(o[u][h], ph[u], vl[2 * h], vl[2 * h + 1]);
                    mma_bf16(o[u][h], pl[u], vh[2 * h], vh[2 * h + 1]);
                }
        }
    }

    if ((tid & 3) == 0) linv[si] = 1.f / lrun;
    __syncthreads();
#pragma unroll
    for (int u = 0; u < 2; u++) {
        int r0 = mi2 + u * 16 + (lane >> 2);
        float i0v = linv[r0], i1v = linv[r0 + 8];
#pragma unroll
        for (int h = 0; h < 2; h++) {
            int col = d0 + h * 8 + (lane & 3) * 2;
            size_t ix0 = ((size_t)(i0 + r0) * BB + b) * 512 + n * 64 + col;
            size_t ix1 = ((size_t)(i0 + r0 + 8) * BB + b) * 512 + n * 64 + col;
            u32 hh, ll;
            hl2(o[u][h][0] * i0v, o[u][h][1] * i0v, hh, ll);
            *(u32*)(oh + ix0) = hh; *(u32*)(ol + ix0) = ll;
            hl2(o[u][h][2] * i1v, o[u][h][3] * i1v, hh, ll);
            *(u32*)(oh + ix1) = hh; *(u32*)(ol + ix1) = ll;
        }
    }
}

// ---------------------------------------------------------------------------
extern "C" void kernel_launch(void* const* d_in, const int* in_sizes, int n_in,
                              void* d_out, int out_size) {
    const float* input = (const float*)d_in[0];
    const float* pos   = (const float*)d_in[1];
    const float* mu    = (const float*)d_in[3];
    const float* rho   = (const float*)d_in[4];
    const float* eps   = (const float*)d_in[5];
    float* out = (float*)d_out;

    float *w, *qkv, *r, *corrg;
    __nv_bfloat16 *ah, *al, *wh, *wl, *qh, *ql, *rh, *rl;
    cudaGetSymbolAddress((void**)&w,    g_w);
    cudaGetSymbolAddress((void**)&qkv,  g_qkv);
    cudaGetSymbolAddress((void**)&r,    g_r);
    cudaGetSymbolAddress((void**)&ah,   g_ah);
    cudaGetSymbolAddress((void**)&al,   g_al);
    cudaGetSymbolAddress((void**)&wh,   g_wh);
    cudaGetSymbolAddress((void**)&wl,   g_wl);
    cudaGetSymbolAddress((void**)&qh,   g_qh);
    cudaGetSymbolAddress((void**)&ql,   g_ql);
    cudaGetSymbolAddress((void**)&rh,   g_rh);
    cudaGetSymbolAddress((void**)&rl,   g_rl);
    cudaGetSymbolAddress((void**)&corrg, g_corr);

    static bool attr_set = false;
    if (!attr_set) {
        cudaFuncSetAttribute(k_hgemm, cudaFuncAttributeMaxDynamicSharedMemorySize, SMEM_G);
        cudaFuncSetAttribute(k_tflash, cudaFuncAttributeMaxDynamicSharedMemorySize, TF_TOT);
        attr_set = true;
    }

    k_sample_w<<<(N_W + 255) / 256, 256>>>(mu, rho, eps, w, wh, wl);

    // qkv = input @ in_w^T + in_b (fused hi/lo split of result)
    k_split<<<(2097152 + 255) / 256, 256>>>(input, ah, al, 2097152);
    k_hgemm<<<dim3(24, 32), 256, SMEM_G>>>(ah, al, wh + OFF_INW, wl + OFF_INW,
                                           w + OFF_INB, qkv, qh, ql, 4096, 1536);

    // r = pos @ pos_w^T + pos_b (fused split) + corr
    k_split<<<(1048576 + 255) / 256, 256>>>(pos, ah, al, 1048576);
    k_hgemm<<<dim3(8, 16), 256, SMEM_G>>>(ah, al, wh + OFF_POSW, wl + OFF_POSW,
                                          w + OFF_POSB, r, rh, rl, 2048, 512);
    k_corr<<<64, 256>>>(r, w, corrg);

    // flash attention -> writes att hi/lo into ah/al
    k_tflash<<<dim3(BB * NHH, 32), 256, TF_TOT>>>(qkv, qh, ql, rh, rl, corrg, w, ah, al);

    // out = att @ out_w^T + out_b
    k_hgemm<<<dim3(8, 32), 256, SMEM_G>>>(ah, al, wh + OFF_OUTW, wl + OFF_OUTW,
                                          w + OFF_OUTB, out, (__nv_bfloat16*)nullptr,
                                          (__nv_bfloat16*)nullptr, 4096, 512);
}